// round 9
// baseline (speedup 1.0000x reference)
#include <cuda_runtime.h>
#include <cuda_bf16.h>
#include <math.h>
#include <stdint.h>

#define EPSV 1e-5f
#define BB 2
#define CC 256
#define C8 32
#define NP 4096          // 16*16*16 positions
#define PADN 5832        // 18*18*18
#define KCONV (CC*27)    // 6912

// ---------------- scratch ----------------
__device__ float g_pad[BB*CC*PADN];
__device__ float g_y[BB*CC*NP];
__device__ float g_out[BB*CC*NP];
__device__ float g_q[BB*C8*NP];
__device__ float g_k[BB*C8*NP];
__device__ float g_v[BB*CC*NP];
__device__ float g_attn[(size_t)BB*NP*NP];           // fp32 energies
__device__ __nv_bfloat16 g_attnh[(size_t)BB*NP*NP];  // bf16 softmaxed attn
__device__ float g_mean[BB*CC];
__device__ float g_rstd[BB*CC];
__device__ float g_wt[CC*KCONV];     // transposed conv weights: wt[co][tap*256+cin]

// padded-offset per conv tap (strides 324/18/1)
__constant__ int c_doff[27] = {
  -343,-342,-341,-325,-324,-323,-307,-306,-305,
   -19, -18, -17,  -1,   0,   1,  17,  18,  19,
   305, 306, 307, 323, 324, 325, 341, 342, 343};

// ---------------- helpers ----------------
__device__ __forceinline__ float tf32r(float x) {
    uint32_t u;
    asm("cvt.rna.tf32.f32 %0, %1;" : "=r"(u) : "f"(x));
    return __uint_as_float(u);
}
__device__ __forceinline__ void mma_tf32(float (&d)[4], const float4 &a, const float2 &b) {
    asm volatile(
        "mma.sync.aligned.m16n8k8.row.col.f32.tf32.tf32.f32 "
        "{%0,%1,%2,%3}, {%4,%5,%6,%7}, {%8,%9}, {%0,%1,%2,%3};\n"
        : "+f"(d[0]), "+f"(d[1]), "+f"(d[2]), "+f"(d[3])
        : "r"(__float_as_uint(a.x)), "r"(__float_as_uint(a.y)),
          "r"(__float_as_uint(a.z)), "r"(__float_as_uint(a.w)),
          "r"(__float_as_uint(b.x)), "r"(__float_as_uint(b.y)));
}
__device__ __forceinline__ void mma_bf16(float (&d)[4], const uint4 &a, const uint2 &b) {
    asm volatile(
        "mma.sync.aligned.m16n8k16.row.col.f32.bf16.bf16.f32 "
        "{%0,%1,%2,%3}, {%4,%5,%6,%7}, {%8,%9}, {%0,%1,%2,%3};\n"
        : "+f"(d[0]), "+f"(d[1]), "+f"(d[2]), "+f"(d[3])
        : "r"(a.x), "r"(a.y), "r"(a.z), "r"(a.w), "r"(b.x), "r"(b.y));
}
__device__ __forceinline__ uint32_t pbf2(float lo, float hi) {
    return (uint32_t)__bfloat16_as_ushort(__float2bfloat16_rn(lo))
         | ((uint32_t)__bfloat16_as_ushort(__float2bfloat16_rn(hi)) << 16);
}
// packed hi parts of (a,b)
__device__ __forceinline__ uint32_t pbf2_hi(float a, float b) { return pbf2(a, b); }
// packed residual lo parts of (a,b)
__device__ __forceinline__ uint32_t pbf2_lo(float a, float b) {
    float ah = __bfloat162float(__float2bfloat16_rn(a));
    float bh = __bfloat162float(__float2bfloat16_rn(b));
    return pbf2(a - ah, b - bh);
}

// ---------------- weight transpose: wt[co][tap*256+cin] = w[co][cin*27+tap] ----------------
__global__ __launch_bounds__(256) void wtrans_kernel(const float* __restrict__ w) {
    int co = blockIdx.x;
    int cin = threadIdx.x;
    const float* src = w + (size_t)co * KCONV + (size_t)cin * 27;
    float v[27];
    #pragma unroll
    for (int t = 0; t < 27; t++) v[t] = src[t];
    float* dst = g_wt + (size_t)co * KCONV + cin;
    #pragma unroll
    for (int t = 0; t < 27; t++) dst[t * 256] = v[t];
}

// ---------------- pad kernel: mode 0: x -> g_pad ; mode 1: instnorm+relu(g_y) -> g_pad
__global__ void pad_kernel(const float* __restrict__ x, int mode) {
    int bc = blockIdx.x;
    const float* src = (mode == 0) ? (x + bc * NP) : (g_y + bc * NP);
    float m = 0.f, r = 1.f;
    if (mode == 1) { m = g_mean[bc]; r = g_rstd[bc]; }
    float* dst = g_pad + bc * PADN;
    for (int i = threadIdx.x; i < PADN; i += blockDim.x) {
        int zp = i % 18; int t = i / 18; int yp = t % 18; int xp = t / 18;
        float v = 0.f;
        if (xp >= 1 && xp <= 16 && yp >= 1 && yp <= 16 && zp >= 1 && zp <= 16) {
            v = src[(xp - 1) * 256 + (yp - 1) * 16 + (zp - 1)];
            if (mode == 1) { v = (v - m) * r; v = v > 0.f ? v : 0.f; }
        }
        dst[i] = v;
    }
}

// ============================================================================
// CONV GEMM, split-bf16 (Ahi*Bhi + Ahi*Blo + Alo*Bhi), m16n8k16, k-chunk 32,
// 2-stage pipeline. A=g_wt[co][(tap,cin)], B=im2col(g_pad), dst=g_y (+bias).
// smem u32 layout per stage: AHI[2048] ALO[2048] BHI[2176] BLO[2176]
// ============================================================================
#define CAHI 0
#define CALO 2048
#define CBHI 4096
#define CBLO 6272
#define CSTG_U32 8448
#define CSMEM (2 * CSTG_U32 * 4)

__global__ __launch_bounds__(256, 1)
void conv_bf16(const float* __restrict__ bias) {
    constexpr int NCH = KCONV / 32;   // 216
    extern __shared__ uint32_t smu[];
    const int tid = threadIdx.x, wid = tid >> 5, lane = tid & 31;
    const int bb = blockIdx.z, m0 = blockIdx.y * 128, n0 = blockIdx.x * 128;
    const int wm = wid & 1, wn = wid >> 1;

    // A loader (tid<128): row-pair (m, m+8), k16 half akb
    const float *av0 = nullptr, *av1 = nullptr;
    uint32_t aoff = 0;
    if (tid < 128) {
        int rpi = tid >> 1, akb = tid & 1;
        int mt = rpi >> 3, rp = rpi & 7;
        int m = m0 + mt * 16 + rp;
        av0 = g_wt + (size_t)m * KCONV + akb * 16;
        av1 = av0 + (size_t)8 * KCONV;
        aoff = mt * 256 + akb * 128 + rp * 16;
    }
    // B loader (all 256): n=bn, k16 block bkb, im2col gather
    const int bn = tid >> 1, bkb = tid & 1;
    int pofs;
    {
        int p = n0 + bn;
        int pz = p & 15, py = (p >> 4) & 15, px = p >> 8;
        pofs = (px + 1) * 324 + (py + 1) * 18 + (pz + 1);
    }
    const float* bbase = g_pad + (size_t)bb * CC * PADN;
    const uint32_t boff = (bn >> 3) * 136 + bkb * 68 + (bn & 7) * 8;

    float a0r[16], a1r[16], br[16];

    #define CLOAD(ch_) do { \
        if (tid < 128) { \
            _Pragma("unroll") \
            for (int q = 0; q < 4; q++) { \
                *(float4*)(a0r + q * 4) = *(const float4*)(av0 + (size_t)(ch_) * 32 + q * 4); \
                *(float4*)(a1r + q * 4) = *(const float4*)(av1 + (size_t)(ch_) * 32 + q * 4); \
            } \
        } \
        _Pragma("unroll") \
        for (int j = 0; j < 16; j++) { \
            int k = (ch_) * 32 + bkb * 16 + j; \
            int tap = k >> 8, cin = k & 255; \
            br[j] = bbase[(size_t)cin * PADN + c_doff[tap] + pofs]; \
        } \
    } while (0)

    #define CSTORE(stg_) do { \
        uint32_t* s_ = smu + (stg_) * CSTG_U32; \
        if (tid < 128) { \
            _Pragma("unroll") \
            for (int t = 0; t < 4; t++) { \
                uint4 wh, wl; \
                wh.x = pbf2_hi(a0r[2*t],   a0r[2*t+1]); wl.x = pbf2_lo(a0r[2*t],   a0r[2*t+1]); \
                wh.y = pbf2_hi(a1r[2*t],   a1r[2*t+1]); wl.y = pbf2_lo(a1r[2*t],   a1r[2*t+1]); \
                wh.z = pbf2_hi(a0r[2*t+8], a0r[2*t+9]); wl.z = pbf2_lo(a0r[2*t+8], a0r[2*t+9]); \
                wh.w = pbf2_hi(a1r[2*t+8], a1r[2*t+9]); wl.w = pbf2_lo(a1r[2*t+8], a1r[2*t+9]); \
                *(uint4*)(s_ + CAHI + aoff + t * 4) = wh; \
                *(uint4*)(s_ + CALO + aoff + t * 4) = wl; \
            } \
        } \
        _Pragma("unroll") \
        for (int t = 0; t < 4; t++) { \
            *(uint2*)(s_ + CBHI + boff + t * 2) = \
                make_uint2(pbf2_hi(br[2*t], br[2*t+1]), pbf2_hi(br[2*t+8], br[2*t+9])); \
            *(uint2*)(s_ + CBLO + boff + t * 2) = \
                make_uint2(pbf2_lo(br[2*t], br[2*t+1]), pbf2_lo(br[2*t+8], br[2*t+9])); \
        } \
    } while (0)

    float acc[4][4][4];
    #pragma unroll
    for (int i = 0; i < 4; i++)
        #pragma unroll
        for (int j = 0; j < 4; j++)
            #pragma unroll
            for (int k = 0; k < 4; k++) acc[i][j][k] = 0.f;

    CLOAD(0); CSTORE(0); CLOAD(1);
    __syncthreads();

    for (int ch = 0; ch < NCH; ch++) {
        int cur = ch & 1;
        if (ch + 1 < NCH) CSTORE(cur ^ 1);
        if (ch + 2 < NCH) CLOAD(ch + 2);

        const uint32_t* s_ = smu + cur * CSTG_U32;
        #pragma unroll
        for (int kb = 0; kb < 2; kb++) {
            uint4 ah[4], al[4]; uint2 bh[4], bl[4];
            #pragma unroll
            for (int mt = 0; mt < 4; mt++) {
                ah[mt] = *(const uint4*)(s_ + CAHI + (wm * 4 + mt) * 256 + kb * 128 + lane * 4);
                al[mt] = *(const uint4*)(s_ + CALO + (wm * 4 + mt) * 256 + kb * 128 + lane * 4);
            }
            #pragma unroll
            for (int nt = 0; nt < 4; nt++) {
                bh[nt] = *(const uint2*)(s_ + CBHI + (wn * 4 + nt) * 136 + kb * 68 + lane * 2);
                bl[nt] = *(const uint2*)(s_ + CBLO + (wn * 4 + nt) * 136 + kb * 68 + lane * 2);
            }
            #pragma unroll
            for (int mt = 0; mt < 4; mt++)
                #pragma unroll
                for (int nt = 0; nt < 4; nt++) {
                    mma_bf16(acc[mt][nt], ah[mt], bh[nt]);
                    mma_bf16(acc[mt][nt], ah[mt], bl[nt]);
                    mma_bf16(acc[mt][nt], al[mt], bh[nt]);
                }
        }
        __syncthreads();
    }

    #undef CLOAD
    #undef CSTORE

    const int g = lane >> 2, tg = lane & 3;
    #pragma unroll
    for (int mt = 0; mt < 4; mt++) {
        int m = m0 + wm * 64 + mt * 16 + g;
        float bs0 = bias[m], bs1 = bias[m + 8];
        #pragma unroll
        for (int nt = 0; nt < 4; nt++) {
            int n = n0 + wn * 32 + nt * 8 + tg * 2;
            size_t base0 = (size_t)(bb * CC + m) * NP + n;
            size_t base1 = base0 + (size_t)8 * NP;
            *(float2*)(g_y + base0) = make_float2(acc[mt][nt][0] + bs0, acc[mt][nt][1] + bs0);
            *(float2*)(g_y + base1) = make_float2(acc[mt][nt][2] + bs1, acc[mt][nt][3] + bs1);
        }
    }
}

// ============================================================================
// tf32 GEMM (kept for VPROJ): A=Aext(wv), B=g_out[c][p], dst=g_v (+bias)
// ============================================================================
#define STG_FLOATS 8320
#define SMEM_DYN (2 * STG_FLOATS * 4)

template<int KTOT>
__global__ __launch_bounds__(256, 1)
void v_gemm_tf32(const float* __restrict__ Aext, const float* __restrict__ bias) {
    constexpr int NCH = KTOT / 32;
    extern __shared__ float sm[];
    const int tid = threadIdx.x, wid = tid >> 5, lane = tid & 31;
    const int bb = blockIdx.z;
    const int m0 = blockIdx.y * 128, n0 = blockIdx.x * 128;

    const int amt = tid >> 5;
    const int arg = (tid >> 2) & 7;
    const int akb = tid & 3;
    const float* aptr0 = Aext + (size_t)(m0 + amt * 16 + arg) * KTOT + akb * 8;
    const float* aptr1 = aptr0 + (size_t)8 * KTOT;

    const int bn = tid >> 1;
    const int bkh = (tid & 1) * 2;
    const float* bbase = g_out + (size_t)bb * CC * NP + n0 + bn;

    float ar0[8], ar1[8], br[16];

    #define LOAD_AB(ch_) do { \
        *(float4*)(ar0)     = *(const float4*)(aptr0 + (size_t)(ch_) * 32); \
        *(float4*)(ar0 + 4) = *(const float4*)(aptr0 + (size_t)(ch_) * 32 + 4); \
        *(float4*)(ar1)     = *(const float4*)(aptr1 + (size_t)(ch_) * 32); \
        *(float4*)(ar1 + 4) = *(const float4*)(aptr1 + (size_t)(ch_) * 32 + 4); \
        _Pragma("unroll") \
        for (int t = 0; t < 2; t++) { \
            _Pragma("unroll") \
            for (int c = 0; c < 8; c++) { \
                int k = (ch_) * 32 + (bkh + t) * 8 + c; \
                br[t * 8 + c] = bbase[(size_t)k * NP]; \
            } \
        } \
    } while (0)

    #define STORE_AB(stg_) do { \
        float* As_ = sm + (stg_) * STG_FLOATS + amt * 512 + akb * 128 + arg * 16; \
        _Pragma("unroll") \
        for (int c = 0; c < 4; c++) { \
            *(float4*)(As_ + c * 4) = make_float4( \
                tf32r(ar0[c]), tf32r(ar1[c]), tf32r(ar0[c + 4]), tf32r(ar1[c + 4])); \
        } \
        float* Bs_ = sm + (stg_) * STG_FLOATS + 4096 + (bn >> 3) * 264 + (bn & 7) * 8; \
        _Pragma("unroll") \
        for (int t = 0; t < 2; t++) { \
            int kbb = bkh + t; \
            _Pragma("unroll") \
            for (int c = 0; c < 4; c++) { \
                *(float2*)(Bs_ + kbb * 64 + c * 2) = \
                    make_float2(tf32r(br[t * 8 + c]), tf32r(br[t * 8 + c + 4])); \
            } \
        } \
    } while (0)

    const int wm = wid & 1, wn = wid >> 1;
    float acc[4][4][4];
    #pragma unroll
    for (int i = 0; i < 4; i++)
        #pragma unroll
        for (int j = 0; j < 4; j++)
            #pragma unroll
            for (int k = 0; k < 4; k++) acc[i][j][k] = 0.f;

    LOAD_AB(0); STORE_AB(0); LOAD_AB(1);
    __syncthreads();

    for (int ch = 0; ch < NCH; ch++) {
        int cur = ch & 1;
        if (ch + 1 < NCH) STORE_AB(cur ^ 1);
        if (ch + 2 < NCH) LOAD_AB(ch + 2);

        const float* As_ = sm + cur * STG_FLOATS;
        const float* Bs_ = As_ + 4096;
        #pragma unroll
        for (int kb = 0; kb < 4; kb++) {
            float4 af[4]; float2 bf[4];
            #pragma unroll
            for (int mt = 0; mt < 4; mt++)
                af[mt] = *(const float4*)(As_ + (wm * 4 + mt) * 512 + kb * 128 + lane * 4);
            #pragma unroll
            for (int nt = 0; nt < 4; nt++)
                bf[nt] = *(const float2*)(Bs_ + (wn * 4 + nt) * 264 + kb * 64 + lane * 2);
            #pragma unroll
            for (int mt = 0; mt < 4; mt++)
                #pragma unroll
                for (int nt = 0; nt < 4; nt++)
                    mma_tf32(acc[mt][nt], af[mt], bf[nt]);
        }
        __syncthreads();
    }

    #undef LOAD_AB
    #undef STORE_AB

    const int g = lane >> 2, tg = lane & 3;
    #pragma unroll
    for (int mt = 0; mt < 4; mt++) {
        int m = m0 + wm * 64 + mt * 16 + g;
        float bs0 = bias[m], bs1 = bias[m + 8];
        #pragma unroll
        for (int nt = 0; nt < 4; nt++) {
            int n = n0 + wn * 32 + nt * 8 + tg * 2;
            size_t base0 = (size_t)(bb * CC + m) * NP + n;
            size_t base1 = base0 + (size_t)8 * NP;
            *(float2*)(g_v + base0) = make_float2(acc[mt][nt][0] + bs0, acc[mt][nt][1] + bs0);
            *(float2*)(g_v + base1) = make_float2(acc[mt][nt][2] + bs1, acc[mt][nt][3] + bs1);
        }
    }
}

// ============================================================================
// o-GEMM, bf16 m16n8k16: o[c,i] = sum_j v[c,j]*attnh[i,j]; dout = gamma*o+g_out
// ============================================================================
#define OA_U32 2048
#define OB_U32 (16*136)
#define OSTG_U32 (OA_U32 + OB_U32)
#define OSMEM (2 * OSTG_U32 * 4)

__global__ __launch_bounds__(256, 1)
void o_gemm_bf16(const float* __restrict__ gamma, float* __restrict__ dout) {
    extern __shared__ uint32_t smu[];
    const int tid = threadIdx.x, wid = tid >> 5, lane = tid & 31;
    const int bb = blockIdx.z, m0 = blockIdx.y * 128, i0 = blockIdx.x * 128;
    const int wm = wid & 1, wn = wid >> 1;

    const float *av0 = nullptr, *av1 = nullptr;
    uint32_t aoff = 0;
    if (tid < 128) {
        int rpi = tid >> 1, akb = tid & 1;
        int mt = rpi >> 3, rp = rpi & 7;
        int m = m0 + mt * 16 + rp;
        av0 = g_v + (size_t)(bb * CC + m) * NP + akb * 16;
        av1 = av0 + (size_t)8 * NP;
        aoff = mt * 256 + akb * 128 + rp * 16;
    }
    const int bn = tid >> 1, bkb = tid & 1;
    const __nv_bfloat16* bptr = g_attnh + ((size_t)bb * NP + i0 + bn) * NP + bkb * 16;
    const uint32_t boff = OA_U32 + (bn >> 3) * 136 + bkb * 68 + (bn & 7) * 8;

    float a0r[16], a1r[16];
    uint32_t brg[8];

    #define OLOAD(ch_) do { \
        if (tid < 128) { \
            _Pragma("unroll") \
            for (int q = 0; q < 4; q++) { \
                *(float4*)(a0r + q * 4) = *(const float4*)(av0 + (size_t)(ch_) * 32 + q * 4); \
                *(float4*)(a1r + q * 4) = *(const float4*)(av1 + (size_t)(ch_) * 32 + q * 4); \
            } \
        } \
        *(uint4*)(brg)     = *(const uint4*)(bptr + (size_t)(ch_) * 32); \
        *(uint4*)(brg + 4) = *(const uint4*)(bptr + (size_t)(ch_) * 32 + 8); \
    } while (0)

    #define OSTORE(stg_) do { \
        uint32_t* s_ = smu + (stg_) * OSTG_U32; \
        if (tid < 128) { \
            _Pragma("unroll") \
            for (int t = 0; t < 4; t++) { \
                uint4 w; \
                w.x = pbf2(a0r[2 * t],     a0r[2 * t + 1]); \
                w.y = pbf2(a1r[2 * t],     a1r[2 * t + 1]); \
                w.z = pbf2(a0r[2 * t + 8], a0r[2 * t + 9]); \
                w.w = pbf2(a1r[2 * t + 8], a1r[2 * t + 9]); \
                *(uint4*)(s_ + aoff + t * 4) = w; \
            } \
        } \
        _Pragma("unroll") \
        for (int t = 0; t < 4; t++) \
            *(uint2*)(s_ + boff + t * 2) = make_uint2(brg[t], brg[t + 4]); \
    } while (0)

    float acc[4][4][4];
    #pragma unroll
    for (int i = 0; i < 4; i++)
        #pragma unroll
        for (int j = 0; j < 4; j++)
            #pragma unroll
            for (int k = 0; k < 4; k++) acc[i][j][k] = 0.f;

    OLOAD(0); OSTORE(0); OLOAD(1);
    __syncthreads();

    constexpr int NCH = NP / 32;   // 128
    for (int ch = 0; ch < NCH; ch++) {
        int cur = ch & 1;
        if (ch + 1 < NCH) OSTORE(cur ^ 1);
        if (ch + 2 < NCH) OLOAD(ch + 2);

        const uint32_t* s_ = smu + cur * OSTG_U32;
        #pragma unroll
        for (int kb = 0; kb < 2; kb++) {
            uint4 af[4]; uint2 bf[4];
            #pragma unroll
            for (int mt = 0; mt < 4; mt++)
                af[mt] = *(const uint4*)(s_ + (wm * 4 + mt) * 256 + kb * 128 + lane * 4);
            #pragma unroll
            for (int nt = 0; nt < 4; nt++)
                bf[nt] = *(const uint2*)(s_ + OA_U32 + (wn * 4 + nt) * 136 + kb * 68 + lane * 2);
            #pragma unroll
            for (int mt = 0; mt < 4; mt++)
                #pragma unroll
                for (int nt = 0; nt < 4; nt++)
                    mma_bf16(acc[mt][nt], af[mt], bf[nt]);
        }
        __syncthreads();
    }

    #undef OLOAD
    #undef OSTORE

    const int g = lane >> 2, tg = lane & 3;
    const float gm = gamma[0];
    #pragma unroll
    for (int mt = 0; mt < 4; mt++) {
        int m = m0 + wm * 64 + mt * 16 + g;
        #pragma unroll
        for (int nt = 0; nt < 4; nt++) {
            int n = i0 + wn * 32 + nt * 8 + tg * 2;
            size_t base0 = (size_t)(bb * CC + m) * NP + n;
            size_t base1 = base0 + (size_t)8 * NP;
            const float* r0 = g_out + base0;
            const float* r1 = g_out + base1;
            *(float2*)(dout + base0) =
                make_float2(gm * acc[mt][nt][0] + r0[0], gm * acc[mt][nt][1] + r0[1]);
            *(float2*)(dout + base1) =
                make_float2(gm * acc[mt][nt][2] + r1[0], gm * acc[mt][nt][3] + r1[1]);
        }
    }
}

// ---------------- stats (reads g_y) ----------------
__global__ void stats_kernel() {
    int bc = blockIdx.x;
    const float* src = g_y + (size_t)bc * NP;
    float s = 0.f, ss = 0.f;
    for (int i = threadIdx.x; i < NP; i += 256) {
        float v = src[i]; s += v; ss += v * v;
    }
    #pragma unroll
    for (int o = 16; o; o >>= 1) {
        s  += __shfl_down_sync(0xffffffffu, s, o);
        ss += __shfl_down_sync(0xffffffffu, ss, o);
    }
    __shared__ float sh_s[8], sh_ss[8];
    int w = threadIdx.x >> 5, l = threadIdx.x & 31;
    if (l == 0) { sh_s[w] = s; sh_ss[w] = ss; }
    __syncthreads();
    if (threadIdx.x == 0) {
        float S = 0.f, SS = 0.f;
        #pragma unroll
        for (int i = 0; i < 8; i++) { S += sh_s[i]; SS += sh_ss[i]; }
        float m = S * (1.0f / NP);
        float var = SS * (1.0f / NP) - m * m;
        g_mean[bc] = m;
        g_rstd[bc] = rsqrtf(var + EPSV);
    }
}

// ---------------- out = x + instnorm(g_y) ----------------
__global__ void norm_add_kernel(const float* __restrict__ x) {
    int idx = blockIdx.x * 256 + threadIdx.x;
    int bc = idx >> 12;
    float m = g_mean[bc], r = g_rstd[bc];
    g_out[idx] = x[idx] + (g_y[idx] - m) * r;
}

// ---------------- energy: energy[b,i,j] = sum_c q[b,c,i]*k[b,c,j], K=32 ----------------
__global__ __launch_bounds__(256) void energy_tc() {
    __shared__ float As[8][2][32][4];
    __shared__ float Bs[16][2][32][2];
    int tid = threadIdx.x, b = blockIdx.z;
    int i0 = blockIdx.y * 128, j0 = blockIdx.x * 128;

    int cl = tid >> 4, ig = tid & 15;
    int ckblk = cl >> 3, ckc = cl & 7;

    int wid = tid >> 5, lane = tid & 31;
    int wm = wid & 1, wn = wid >> 1;

    float acc[4][4][4];
    #pragma unroll
    for (int i = 0; i < 4; i++)
        #pragma unroll
        for (int j = 0; j < 4; j++)
            #pragma unroll
            for (int k = 0; k < 4; k++) acc[i][j][k] = 0.f;

    #pragma unroll
    for (int it = 0; it < 2; ++it) {
        int c = it * 16 + cl;
        const float* qsrc = g_q + (size_t)(b * C8 + c) * NP + i0 + ig * 8;
        const float* ksrc = g_k + (size_t)(b * C8 + c) * NP + j0 + ig * 8;
        float4 q0 = *(const float4*)qsrc, q1 = *(const float4*)(qsrc + 4);
        float4 k0 = *(const float4*)ksrc, k1 = *(const float4*)(ksrc + 4);

        __syncthreads();
        {
            float qv[8] = {q0.x, q0.y, q0.z, q0.w, q1.x, q1.y, q1.z, q1.w};
            #pragma unroll
            for (int ii = 0; ii < 8; ii++) {
                int r = ig * 8 + ii;
                int mtile = r >> 4, rr = r & 15;
                As[mtile][ckblk][(rr & 7) * 4 + (ckc & 3)][(rr >> 3) + ((ckc >> 2) << 1)] = tf32r(qv[ii]);
            }
            float kv[8] = {k0.x, k0.y, k0.z, k0.w, k1.x, k1.y, k1.z, k1.w};
            #pragma unroll
            for (int nn = 0; nn < 8; nn++)
                Bs[ig][ckblk][nn * 4 + (ckc & 3)][ckc >> 2] = tf32r(kv[nn]);
        }
        __syncthreads();

        #pragma unroll
        for (int kb = 0; kb < 2; kb++) {
            float4 af[4]; float2 bf[4];
            #pragma unroll
            for (int mt = 0; mt < 4; mt++) af[mt] = *(const float4*)As[wm * 4 + mt][kb][lane];
            #pragma unroll
            for (int nt = 0; nt < 4; nt++) bf[nt] = *(const float2*)Bs[wn * 4 + nt][kb][lane];
            #pragma unroll
            for (int mt = 0; mt < 4; mt++)
                #pragma unroll
                for (int nt = 0; nt < 4; nt++)
                    mma_tf32(acc[mt][nt], af[mt], bf[nt]);
        }
    }

    int g = lane >> 2, tg = lane & 3;
    #pragma unroll
    for (int mt = 0; mt < 4; mt++) {
        int m = i0 + wm * 64 + mt * 16 + g;
        #pragma unroll
        for (int nt = 0; nt < 4; nt++) {
            int n = j0 + wn * 32 + nt * 8 + tg * 2;
            float* d0 = g_attn + ((size_t)b * NP + m) * NP + n;
            *(float2*)d0 = make_float2(acc[mt][nt][0], acc[mt][nt][1]);
            *(float2*)(d0 + (size_t)8 * NP) = make_float2(acc[mt][nt][2], acc[mt][nt][3]);
        }
    }
}

// ---------------- q and k projections fused (FFMA, small) ----------------
__global__ __launch_bounds__(256) void qk_gemm(const float* __restrict__ wq, const float* __restrict__ bq,
                                               const float* __restrict__ wk, const float* __restrict__ bk) {
    __shared__ float As[8][64];
    __shared__ float Bs[8][128];
    int tid = threadIdx.x, b = blockIdx.z;
    int p0 = blockIdx.x * 128;
    int arow = tid >> 2;
    int acol = (tid & 3) * 2;
    const float* ap = ((arow < 32) ? (wq + arow * CC) : (wk + (arow - 32) * CC)) + acol;
    int brow = tid >> 5, bcol = (tid & 31) * 4;
    const float* bp = g_out + (b * CC + brow) * NP + p0 + bcol;
    int ty = tid >> 4, tx = tid & 15;
    float acc[4][8];
    #pragma unroll
    for (int i = 0; i < 4; i++)
        #pragma unroll
        for (int j = 0; j < 8; j++) acc[i][j] = 0.f;

    for (int it = 0; it < CC / 8; ++it) {
        float2 av = *(const float2*)(ap + it * 8);
        float4 bv = *(const float4*)(bp + (size_t)it * 8 * NP);
        __syncthreads();
        As[acol + 0][arow] = av.x;
        As[acol + 1][arow] = av.y;
        *(float4*)&Bs[brow][bcol] = bv;
        __syncthreads();
        #pragma unroll
        for (int kk = 0; kk < 8; kk++) {
            float a[4], bvv[8];
            float4 t0 = *(const float4*)&As[kk][ty * 4];
            a[0]=t0.x; a[1]=t0.y; a[2]=t0.z; a[3]=t0.w;
            float4 u0 = *(const float4*)&Bs[kk][tx * 8];
            float4 u1 = *(const float4*)&Bs[kk][tx * 8 + 4];
            bvv[0]=u0.x; bvv[1]=u0.y; bvv[2]=u0.z; bvv[3]=u0.w;
            bvv[4]=u1.x; bvv[5]=u1.y; bvv[6]=u1.z; bvv[7]=u1.w;
            #pragma unroll
            for (int i = 0; i < 4; i++)
                #pragma unroll
                for (int j = 0; j < 8; j++)
                    acc[i][j] += a[i] * bvv[j];
        }
    }
    #pragma unroll
    for (int i = 0; i < 4; i++) {
        int row = ty * 4 + i;
        float bias = (row < 32) ? bq[row] : bk[row - 32];
        float* dst = ((row < 32) ? (g_q + (b * C8 + row) * NP)
                                 : (g_k + (b * C8 + row - 32) * NP)) + p0 + tx * 8;
        *(float4*)dst       = make_float4(acc[i][0]+bias, acc[i][1]+bias, acc[i][2]+bias, acc[i][3]+bias);
        *(float4*)(dst + 4) = make_float4(acc[i][4]+bias, acc[i][5]+bias, acc[i][6]+bias, acc[i][7]+bias);
    }
}

// ---------------- row softmax over 4096: fp32 in -> bf16 out ----------------
__global__ __launch_bounds__(256) void softmax_kernel() {
    size_t row = blockIdx.x;
    const float* ptr = g_attn + row * (size_t)NP;
    __nv_bfloat16* op = g_attnh + row * (size_t)NP;
    int tid = threadIdx.x;
    float vals[16];
    float m = -1e30f;
    #pragma unroll
    for (int s = 0; s < 16; s++) {
        vals[s] = ptr[tid + s * 256];
        m = fmaxf(m, vals[s]);
    }
    #pragma unroll
    for (int o = 16; o; o >>= 1) m = fmaxf(m, __shfl_xor_sync(0xffffffffu, m, o));
    __shared__ float shm[8], shs[8];
    int w = tid >> 5, l = tid & 31;
    if (l == 0) shm[w] = m;
    __syncthreads();
    m = fmaxf(fmaxf(fmaxf(shm[0], shm[1]), fmaxf(shm[2], shm[3])),
              fmaxf(fmaxf(shm[4], shm[5]), fmaxf(shm[6], shm[7])));
    float sum = 0.f;
    #pragma unroll
    for (int s = 0; s < 16; s++) {
        vals[s] = __expf(vals[s] - m);
        sum += vals[s];
    }
    #pragma unroll
    for (int o = 16; o; o >>= 1) sum += __shfl_xor_sync(0xffffffffu, sum, o);
    if (l == 0) shs[w] = sum;
    __syncthreads();
    sum = shs[0] + shs[1] + shs[2] + shs[3] + shs[4] + shs[5] + shs[6] + shs[7];
    float inv = 1.0f / sum;
    #pragma unroll
    for (int s = 0; s < 16; s++)
        op[tid + s * 256] = __float2bfloat16_rn(vals[s] * inv);
}

// ---------------- launcher ----------------
extern "C" void kernel_launch(void* const* d_in, const int* in_sizes, int n_in,
                              void* d_out, int out_size) {
    const float* x     = (const float*)d_in[0];
    const float* w1    = (const float*)d_in[1];
    const float* b1    = (const float*)d_in[2];
    const float* w2    = (const float*)d_in[3];
    const float* b2    = (const float*)d_in[4];
    const float* wq    = (const float*)d_in[5];
    const float* bq    = (const float*)d_in[6];
    const float* wk    = (const float*)d_in[7];
    const float* bk    = (const float*)d_in[8];
    const float* wv    = (const float*)d_in[9];
    const float* bv    = (const float*)d_in[10];
    const float* gamma = (const float*)d_in[11];
    float* out = (float*)d_out;

    cudaFuncSetAttribute(conv_bf16,       cudaFuncAttributeMaxDynamicSharedMemorySize, CSMEM);
    cudaFuncSetAttribute(v_gemm_tf32<CC>, cudaFuncAttributeMaxDynamicSharedMemorySize, SMEM_DYN);
    cudaFuncSetAttribute(o_gemm_bf16,     cudaFuncAttributeMaxDynamicSharedMemorySize, OSMEM);

    dim3 g128(NP / 128, CC / 128, BB);   // (32,2,2)

    // conv block (split-bf16 conv GEMMs)
    pad_kernel<<<BB * CC, 256>>>(x, 0);
    wtrans_kernel<<<CC, 256>>>(w1);
    conv_bf16<<<g128, 256, CSMEM>>>(b1);
    stats_kernel<<<BB * CC, 256>>>();
    pad_kernel<<<BB * CC, 256>>>(nullptr, 1);      // instnorm + relu + pad
    wtrans_kernel<<<CC, 256>>>(w2);
    conv_bf16<<<g128, 256, CSMEM>>>(b2);
    stats_kernel<<<BB * CC, 256>>>();
    norm_add_kernel<<<BB * CC * NP / 256, 256>>>(x);

    // attention
    qk_gemm<<<dim3(NP / 128, 1, BB), 256>>>(wq, bq, wk, bk);
    v_gemm_tf32<CC><<<g128, 256, SMEM_DYN>>>(wv, bv);
    energy_tc<<<dim3(NP / 128, NP / 128, BB), 256>>>();
    softmax_kernel<<<BB * NP, 256>>>();
    o_gemm_bf16<<<g128, 256, OSMEM>>>(gamma, out);
}

// round 10
// speedup vs baseline: 1.2221x; 1.2221x over previous
#include <cuda_runtime.h>
#include <cuda_bf16.h>
#include <math.h>
#include <stdint.h>

#define EPSV 1e-5f
#define BB 2
#define CC 256
#define C8 32
#define NP 4096          // 16*16*16 positions
#define PADN 5832        // 18*18*18
#define KCONV (CC*27)    // 6912

// ---------------- scratch ----------------
__device__ float g_pad[BB*CC*PADN];
__device__ float g_y[BB*CC*NP];
__device__ float g_out[BB*CC*NP];
__device__ float g_q[BB*C8*NP];
__device__ float g_k[BB*C8*NP];
__device__ float g_v[BB*CC*NP];
__device__ __nv_bfloat16 g_attnh[(size_t)BB*NP*NP];  // bf16 energies -> softmaxed in place
__device__ float g_wt[CC*KCONV];     // transposed conv weights: wt[co][tap*256+cin]

// padded-offset per conv tap (strides 324/18/1)
__constant__ int c_doff[27] = {
  -343,-342,-341,-325,-324,-323,-307,-306,-305,
   -19, -18, -17,  -1,   0,   1,  17,  18,  19,
   305, 306, 307, 323, 324, 325, 341, 342, 343};

// ---------------- helpers ----------------
__device__ __forceinline__ float tf32r(float x) {
    uint32_t u;
    asm("cvt.rna.tf32.f32 %0, %1;" : "=r"(u) : "f"(x));
    return __uint_as_float(u);
}
__device__ __forceinline__ void mma_tf32(float (&d)[4], const float4 &a, const float2 &b) {
    asm volatile(
        "mma.sync.aligned.m16n8k8.row.col.f32.tf32.tf32.f32 "
        "{%0,%1,%2,%3}, {%4,%5,%6,%7}, {%8,%9}, {%0,%1,%2,%3};\n"
        : "+f"(d[0]), "+f"(d[1]), "+f"(d[2]), "+f"(d[3])
        : "r"(__float_as_uint(a.x)), "r"(__float_as_uint(a.y)),
          "r"(__float_as_uint(a.z)), "r"(__float_as_uint(a.w)),
          "r"(__float_as_uint(b.x)), "r"(__float_as_uint(b.y)));
}
__device__ __forceinline__ void mma_bf16(float (&d)[4], const uint4 &a, const uint2 &b) {
    asm volatile(
        "mma.sync.aligned.m16n8k16.row.col.f32.bf16.bf16.f32 "
        "{%0,%1,%2,%3}, {%4,%5,%6,%7}, {%8,%9}, {%0,%1,%2,%3};\n"
        : "+f"(d[0]), "+f"(d[1]), "+f"(d[2]), "+f"(d[3])
        : "r"(a.x), "r"(a.y), "r"(a.z), "r"(a.w), "r"(b.x), "r"(b.y));
}
__device__ __forceinline__ uint32_t pbf2(float lo, float hi) {
    return (uint32_t)__bfloat16_as_ushort(__float2bfloat16_rn(lo))
         | ((uint32_t)__bfloat16_as_ushort(__float2bfloat16_rn(hi)) << 16);
}

// ---------------- weight transpose: wt[co][tap*256+cin] = w[co][cin*27+tap] ----------------
__global__ __launch_bounds__(256) void wtrans_kernel(const float* __restrict__ w) {
    int co = blockIdx.x;
    int cin = threadIdx.x;
    const float* src = w + (size_t)co * KCONV + (size_t)cin * 27;
    float v[27];
    #pragma unroll
    for (int t = 0; t < 27; t++) v[t] = src[t];
    float* dst = g_wt + (size_t)co * KCONV + cin;
    #pragma unroll
    for (int t = 0; t < 27; t++) dst[t * 256] = v[t];
}

// ---------------- pad kernel: x -> g_pad (zero-padded copy) ----------------
__global__ void pad_kernel(const float* __restrict__ x) {
    int bc = blockIdx.x;
    const float* src = x + bc * NP;
    float* dst = g_pad + bc * PADN;
    for (int i = threadIdx.x; i < PADN; i += blockDim.x) {
        int zp = i % 18; int t = i / 18; int yp = t % 18; int xp = t / 18;
        float v = 0.f;
        if (xp >= 1 && xp <= 16 && yp >= 1 && yp <= 16 && zp >= 1 && zp <= 16)
            v = src[(xp - 1) * 256 + (yp - 1) * 16 + (zp - 1)];
        dst[i] = v;
    }
}

// ---------------- block-wide mean/rstd of g_y[bc] (broadcast via smem) ----------------
__device__ __forceinline__ void block_stats(const float* __restrict__ src,
                                            float& mean, float& rstd) {
    float s = 0.f, ss = 0.f;
    for (int i = threadIdx.x; i < NP; i += 256) {
        float v = src[i]; s += v; ss += v * v;
    }
    #pragma unroll
    for (int o = 16; o; o >>= 1) {
        s  += __shfl_down_sync(0xffffffffu, s, o);
        ss += __shfl_down_sync(0xffffffffu, ss, o);
    }
    __shared__ float sh_s[8], sh_ss[8], sh_m, sh_r;
    int w = threadIdx.x >> 5, l = threadIdx.x & 31;
    if (l == 0) { sh_s[w] = s; sh_ss[w] = ss; }
    __syncthreads();
    if (threadIdx.x == 0) {
        float S = 0.f, SS = 0.f;
        #pragma unroll
        for (int i = 0; i < 8; i++) { S += sh_s[i]; SS += sh_ss[i]; }
        float m = S * (1.0f / NP);
        float var = SS * (1.0f / NP) - m * m;
        sh_m = m;
        sh_r = rsqrtf(var + EPSV);
    }
    __syncthreads();
    mean = sh_m; rstd = sh_r;
}

// ---------------- fused: stats(g_y[bc]) then instnorm+relu+pad -> g_pad ----------------
__global__ void stats_pad_kernel() {
    int bc = blockIdx.x;
    const float* src = g_y + (size_t)bc * NP;
    float m, r;
    block_stats(src, m, r);
    float* dst = g_pad + (size_t)bc * PADN;
    for (int i = threadIdx.x; i < PADN; i += 256) {
        int zp = i % 18; int t = i / 18; int yp = t % 18; int xp = t / 18;
        float v = 0.f;
        if (xp >= 1 && xp <= 16 && yp >= 1 && yp <= 16 && zp >= 1 && zp <= 16) {
            v = src[(xp - 1) * 256 + (yp - 1) * 16 + (zp - 1)];
            v = fmaxf((v - m) * r, 0.f);
        }
        dst[i] = v;
    }
}

// ---------------- fused: stats(g_y[bc]) then g_out = x + instnorm(g_y) ----------------
__global__ void stats_norm_kernel(const float* __restrict__ x) {
    int bc = blockIdx.x;
    const float* src = g_y + (size_t)bc * NP;
    float m, r;
    block_stats(src, m, r);
    const float* xb = x + (size_t)bc * NP;
    float* dst = g_out + (size_t)bc * NP;
    for (int i = threadIdx.x; i < NP; i += 256)
        dst[i] = xb[i] + (src[i] - m) * r;
}

// ============================================================================
// Pipelined mma.sync tf32 GEMM, 128x128 tile, k-step 32, 2-stage smem.
// MODE 0 (CONV):  A=g_wt[co][(tap,cin)], B=im2col(g_pad), dst=g_y (+bias)
// MODE 1 (VPROJ): A=Aext(wv),            B=g_out[c][p],   dst=g_v (+bias)
// ============================================================================
#define STG_FLOATS 8320
#define SMEM_DYN (2 * STG_FLOATS * 4)

template<int MODE, int KTOT>
__global__ __launch_bounds__(256, 1)
void tc_gemm(const float* __restrict__ Aext, const float* __restrict__ bias) {
    constexpr int NCH = KTOT / 32;
    extern __shared__ float sm[];
    const int tid = threadIdx.x, wid = tid >> 5, lane = tid & 31;
    const int bb = blockIdx.z;
    const int m0 = blockIdx.y * 128, n0 = blockIdx.x * 128;

    // ---- A loader ----
    const int amt = tid >> 5;
    const int arg = (tid >> 2) & 7;
    const int akb = tid & 3;
    const float* aptr0;
    const float* aptr1;
    {
        int m = m0 + amt * 16 + arg;
        const float* base = (MODE == 0) ? g_wt : Aext;
        aptr0 = base + (size_t)m * KTOT + akb * 8;
        aptr1 = base + (size_t)(m + 8) * KTOT + akb * 8;
    }

    // ---- B loader ----
    const int bn = tid >> 1;
    const int bkh = (tid & 1) * 2;
    int pofs = 0;
    const float* bbase = nullptr;
    if (MODE == 0) {
        int p = n0 + bn;
        int pz = p & 15, py = (p >> 4) & 15, px = p >> 8;
        pofs = (px + 1) * 324 + (py + 1) * 18 + (pz + 1);
        bbase = g_pad + (size_t)bb * CC * PADN;
    } else {
        bbase = g_out + (size_t)bb * CC * NP + n0 + bn;
    }

    float ar0[8], ar1[8], br[16];

    #define LOAD_A(ch_) do { \
        *(float4*)(ar0)     = *(const float4*)(aptr0 + (size_t)(ch_) * 32); \
        *(float4*)(ar0 + 4) = *(const float4*)(aptr0 + (size_t)(ch_) * 32 + 4); \
        *(float4*)(ar1)     = *(const float4*)(aptr1 + (size_t)(ch_) * 32); \
        *(float4*)(ar1 + 4) = *(const float4*)(aptr1 + (size_t)(ch_) * 32 + 4); \
    } while (0)

    #define LOAD_B(ch_) do { \
        if (MODE == 0) { \
            _Pragma("unroll") \
            for (int t = 0; t < 2; t++) { \
                _Pragma("unroll") \
                for (int c = 0; c < 8; c++) { \
                    int k = (ch_) * 32 + (bkh + t) * 8 + c; \
                    int tap = k >> 8, cin = k & 255; \
                    br[t * 8 + c] = bbase[(size_t)cin * PADN + c_doff[tap] + pofs]; \
                } \
            } \
        } else { \
            _Pragma("unroll") \
            for (int t = 0; t < 2; t++) { \
                _Pragma("unroll") \
                for (int c = 0; c < 8; c++) { \
                    int k = (ch_) * 32 + (bkh + t) * 8 + c; \
                    br[t * 8 + c] = bbase[(size_t)k * NP]; \
                } \
            } \
        } \
    } while (0)

    #define STORE_AB(stg_) do { \
        float* As_ = sm + (stg_) * STG_FLOATS + amt * 512 + akb * 128 + arg * 16; \
        _Pragma("unroll") \
        for (int c = 0; c < 4; c++) { \
            *(float4*)(As_ + c * 4) = make_float4( \
                tf32r(ar0[c]), tf32r(ar1[c]), tf32r(ar0[c + 4]), tf32r(ar1[c + 4])); \
        } \
        float* Bs_ = sm + (stg_) * STG_FLOATS + 4096 + (bn >> 3) * 264 + (bn & 7) * 8; \
        _Pragma("unroll") \
        for (int t = 0; t < 2; t++) { \
            int kbb = bkh + t; \
            _Pragma("unroll") \
            for (int c = 0; c < 4; c++) { \
                *(float2*)(Bs_ + kbb * 64 + c * 2) = \
                    make_float2(tf32r(br[t * 8 + c]), tf32r(br[t * 8 + c + 4])); \
            } \
        } \
    } while (0)

    const int wm = wid & 1, wn = wid >> 1;
    float acc[4][4][4];
    #pragma unroll
    for (int i = 0; i < 4; i++)
        #pragma unroll
        for (int j = 0; j < 4; j++)
            #pragma unroll
            for (int k = 0; k < 4; k++) acc[i][j][k] = 0.f;

    LOAD_A(0); LOAD_B(0);
    STORE_AB(0);
    LOAD_A(1); LOAD_B(1);
    __syncthreads();

    for (int ch = 0; ch < NCH; ch++) {
        int cur = ch & 1;
        if (ch + 1 < NCH) STORE_AB(cur ^ 1);
        if (ch + 2 < NCH) { LOAD_A(ch + 2); LOAD_B(ch + 2); }

        const float* As_ = sm + cur * STG_FLOATS;
        const float* Bs_ = As_ + 4096;
        #pragma unroll
        for (int kb = 0; kb < 4; kb++) {
            float4 af[4]; float2 bf[4];
            #pragma unroll
            for (int mt = 0; mt < 4; mt++)
                af[mt] = *(const float4*)(As_ + (wm * 4 + mt) * 512 + kb * 128 + lane * 4);
            #pragma unroll
            for (int nt = 0; nt < 4; nt++)
                bf[nt] = *(const float2*)(Bs_ + (wn * 4 + nt) * 264 + kb * 64 + lane * 2);
            #pragma unroll
            for (int mt = 0; mt < 4; mt++)
                #pragma unroll
                for (int nt = 0; nt < 4; nt++)
                    mma_tf32(acc[mt][nt], af[mt], bf[nt]);
        }
        __syncthreads();
    }

    #undef LOAD_A
    #undef LOAD_B
    #undef STORE_AB

    const int g = lane >> 2, tg = lane & 3;
    float* dst = (MODE == 0) ? g_y : g_v;
    #pragma unroll
    for (int mt = 0; mt < 4; mt++) {
        int m = m0 + wm * 64 + mt * 16 + g;
        float bs0 = bias[m], bs1 = bias[m + 8];
        #pragma unroll
        for (int nt = 0; nt < 4; nt++) {
            int n = n0 + wn * 32 + nt * 8 + tg * 2;
            size_t base0 = (size_t)(bb * CC + m) * NP + n;
            size_t base1 = base0 + (size_t)8 * NP;
            *(float2*)(dst + base0) = make_float2(acc[mt][nt][0] + bs0, acc[mt][nt][1] + bs0);
            *(float2*)(dst + base1) = make_float2(acc[mt][nt][2] + bs1, acc[mt][nt][3] + bs1);
        }
    }
}

// ============================================================================
// o-GEMM, bf16 m16n8k16: o[c,i] = sum_j v[c,j]*attnh[i,j]; dout = gamma*o+g_out
// ============================================================================
#define OA_U32 2048
#define OB_U32 (16*136)
#define OSTG_U32 (OA_U32 + OB_U32)
#define OSMEM (2 * OSTG_U32 * 4)

__global__ __launch_bounds__(256, 1)
void o_gemm_bf16(const float* __restrict__ gamma, float* __restrict__ dout) {
    extern __shared__ uint32_t smu[];
    const int tid = threadIdx.x, wid = tid >> 5, lane = tid & 31;
    const int bb = blockIdx.z, m0 = blockIdx.y * 128, i0 = blockIdx.x * 128;
    const int wm = wid & 1, wn = wid >> 1;

    const float *av0 = nullptr, *av1 = nullptr;
    uint32_t aoff = 0;
    if (tid < 128) {
        int rpi = tid >> 1, akb = tid & 1;
        int mt = rpi >> 3, rp = rpi & 7;
        int m = m0 + mt * 16 + rp;
        av0 = g_v + (size_t)(bb * CC + m) * NP + akb * 16;
        av1 = av0 + (size_t)8 * NP;
        aoff = mt * 256 + akb * 128 + rp * 16;
    }
    const int bn = tid >> 1, bkb = tid & 1;
    const __nv_bfloat16* bptr = g_attnh + ((size_t)bb * NP + i0 + bn) * NP + bkb * 16;
    const uint32_t boff = OA_U32 + (bn >> 3) * 136 + bkb * 68 + (bn & 7) * 8;

    float a0r[16], a1r[16];
    uint32_t brg[8];

    #define OLOAD(ch_) do { \
        if (tid < 128) { \
            _Pragma("unroll") \
            for (int q = 0; q < 4; q++) { \
                *(float4*)(a0r + q * 4) = *(const float4*)(av0 + (size_t)(ch_) * 32 + q * 4); \
                *(float4*)(a1r + q * 4) = *(const float4*)(av1 + (size_t)(ch_) * 32 + q * 4); \
            } \
        } \
        *(uint4*)(brg)     = *(const uint4*)(bptr + (size_t)(ch_) * 32); \
        *(uint4*)(brg + 4) = *(const uint4*)(bptr + (size_t)(ch_) * 32 + 8); \
    } while (0)

    #define OSTORE(stg_) do { \
        uint32_t* s_ = smu + (stg_) * OSTG_U32; \
        if (tid < 128) { \
            _Pragma("unroll") \
            for (int t = 0; t < 4; t++) { \
                uint4 w; \
                w.x = pbf2(a0r[2 * t],     a0r[2 * t + 1]); \
                w.y = pbf2(a1r[2 * t],     a1r[2 * t + 1]); \
                w.z = pbf2(a0r[2 * t + 8], a0r[2 * t + 9]); \
                w.w = pbf2(a1r[2 * t + 8], a1r[2 * t + 9]); \
                *(uint4*)(s_ + aoff + t * 4) = w; \
            } \
        } \
        _Pragma("unroll") \
        for (int t = 0; t < 4; t++) \
            *(uint2*)(s_ + boff + t * 2) = make_uint2(brg[t], brg[t + 4]); \
    } while (0)

    float acc[4][4][4];
    #pragma unroll
    for (int i = 0; i < 4; i++)
        #pragma unroll
        for (int j = 0; j < 4; j++)
            #pragma unroll
            for (int k = 0; k < 4; k++) acc[i][j][k] = 0.f;

    OLOAD(0); OSTORE(0); OLOAD(1);
    __syncthreads();

    constexpr int NCH = NP / 32;   // 128
    for (int ch = 0; ch < NCH; ch++) {
        int cur = ch & 1;
        if (ch + 1 < NCH) OSTORE(cur ^ 1);
        if (ch + 2 < NCH) OLOAD(ch + 2);

        const uint32_t* s_ = smu + cur * OSTG_U32;
        #pragma unroll
        for (int kb = 0; kb < 2; kb++) {
            uint4 af[4]; uint2 bf[4];
            #pragma unroll
            for (int mt = 0; mt < 4; mt++)
                af[mt] = *(const uint4*)(s_ + (wm * 4 + mt) * 256 + kb * 128 + lane * 4);
            #pragma unroll
            for (int nt = 0; nt < 4; nt++)
                bf[nt] = *(const uint2*)(s_ + OA_U32 + (wn * 4 + nt) * 136 + kb * 68 + lane * 2);
            #pragma unroll
            for (int mt = 0; mt < 4; mt++)
                #pragma unroll
                for (int nt = 0; nt < 4; nt++)
                    mma_bf16(acc[mt][nt], af[mt], bf[nt]);
        }
        __syncthreads();
    }

    #undef OLOAD
    #undef OSTORE

    const int g = lane >> 2, tg = lane & 3;
    const float gm = gamma[0];
    #pragma unroll
    for (int mt = 0; mt < 4; mt++) {
        int m = m0 + wm * 64 + mt * 16 + g;
        #pragma unroll
        for (int nt = 0; nt < 4; nt++) {
            int n = i0 + wn * 32 + nt * 8 + tg * 2;
            size_t base0 = (size_t)(bb * CC + m) * NP + n;
            size_t base1 = base0 + (size_t)8 * NP;
            const float* r0 = g_out + base0;
            const float* r1 = g_out + base1;
            *(float2*)(dout + base0) =
                make_float2(gm * acc[mt][nt][0] + r0[0], gm * acc[mt][nt][1] + r0[1]);
            *(float2*)(dout + base1) =
                make_float2(gm * acc[mt][nt][2] + r1[0], gm * acc[mt][nt][3] + r1[1]);
        }
    }
}

// ---------------- energy -> bf16 g_attnh: energy[b,i,j] = sum_c q[b,c,i]*k[b,c,j] ----------------
__global__ __launch_bounds__(256) void energy_tc() {
    __shared__ float As[8][2][32][4];
    __shared__ float Bs[16][2][32][2];
    int tid = threadIdx.x, b = blockIdx.z;
    int i0 = blockIdx.y * 128, j0 = blockIdx.x * 128;

    int cl = tid >> 4, ig = tid & 15;
    int ckblk = cl >> 3, ckc = cl & 7;

    int wid = tid >> 5, lane = tid & 31;
    int wm = wid & 1, wn = wid >> 1;

    float acc[4][4][4];
    #pragma unroll
    for (int i = 0; i < 4; i++)
        #pragma unroll
        for (int j = 0; j < 4; j++)
            #pragma unroll
            for (int k = 0; k < 4; k++) acc[i][j][k] = 0.f;

    #pragma unroll
    for (int it = 0; it < 2; ++it) {
        int c = it * 16 + cl;
        const float* qsrc = g_q + (size_t)(b * C8 + c) * NP + i0 + ig * 8;
        const float* ksrc = g_k + (size_t)(b * C8 + c) * NP + j0 + ig * 8;
        float4 q0 = *(const float4*)qsrc, q1 = *(const float4*)(qsrc + 4);
        float4 k0 = *(const float4*)ksrc, k1 = *(const float4*)(ksrc + 4);

        __syncthreads();
        {
            float qv[8] = {q0.x, q0.y, q0.z, q0.w, q1.x, q1.y, q1.z, q1.w};
            #pragma unroll
            for (int ii = 0; ii < 8; ii++) {
                int r = ig * 8 + ii;
                int mtile = r >> 4, rr = r & 15;
                As[mtile][ckblk][(rr & 7) * 4 + (ckc & 3)][(rr >> 3) + ((ckc >> 2) << 1)] = tf32r(qv[ii]);
            }
            float kv[8] = {k0.x, k0.y, k0.z, k0.w, k1.x, k1.y, k1.z, k1.w};
            #pragma unroll
            for (int nn = 0; nn < 8; nn++)
                Bs[ig][ckblk][nn * 4 + (ckc & 3)][ckc >> 2] = tf32r(kv[nn]);
        }
        __syncthreads();

        #pragma unroll
        for (int kb = 0; kb < 2; kb++) {
            float4 af[4]; float2 bf[4];
            #pragma unroll
            for (int mt = 0; mt < 4; mt++) af[mt] = *(const float4*)As[wm * 4 + mt][kb][lane];
            #pragma unroll
            for (int nt = 0; nt < 4; nt++) bf[nt] = *(const float2*)Bs[wn * 4 + nt][kb][lane];
            #pragma unroll
            for (int mt = 0; mt < 4; mt++)
                #pragma unroll
                for (int nt = 0; nt < 4; nt++)
                    mma_tf32(acc[mt][nt], af[mt], bf[nt]);
        }
    }

    int g = lane >> 2, tg = lane & 3;
    #pragma unroll
    for (int mt = 0; mt < 4; mt++) {
        int m = i0 + wm * 64 + mt * 16 + g;
        #pragma unroll
        for (int nt = 0; nt < 4; nt++) {
            int n = j0 + wn * 32 + nt * 8 + tg * 2;
            __nv_bfloat16* d0 = g_attnh + ((size_t)b * NP + m) * NP + n;
            *(uint32_t*)d0 = pbf2(acc[mt][nt][0], acc[mt][nt][1]);
            *(uint32_t*)(d0 + (size_t)8 * NP) = pbf2(acc[mt][nt][2], acc[mt][nt][3]);
        }
    }
}

// ---------------- q and k projections fused (FFMA, small) ----------------
__global__ __launch_bounds__(256) void qk_gemm(const float* __restrict__ wq, const float* __restrict__ bq,
                                               const float* __restrict__ wk, const float* __restrict__ bk) {
    __shared__ float As[8][64];
    __shared__ float Bs[8][128];
    int tid = threadIdx.x, b = blockIdx.z;
    int p0 = blockIdx.x * 128;
    int arow = tid >> 2;
    int acol = (tid & 3) * 2;
    const float* ap = ((arow < 32) ? (wq + arow * CC) : (wk + (arow - 32) * CC)) + acol;
    int brow = tid >> 5, bcol = (tid & 31) * 4;
    const float* bp = g_out + (b * CC + brow) * NP + p0 + bcol;
    int ty = tid >> 4, tx = tid & 15;
    float acc[4][8];
    #pragma unroll
    for (int i = 0; i < 4; i++)
        #pragma unroll
        for (int j = 0; j < 8; j++) acc[i][j] = 0.f;

    for (int it = 0; it < CC / 8; ++it) {
        float2 av = *(const float2*)(ap + it * 8);
        float4 bv = *(const float4*)(bp + (size_t)it * 8 * NP);
        __syncthreads();
        As[acol + 0][arow] = av.x;
        As[acol + 1][arow] = av.y;
        *(float4*)&Bs[brow][bcol] = bv;
        __syncthreads();
        #pragma unroll
        for (int kk = 0; kk < 8; kk++) {
            float a[4], bvv[8];
            float4 t0 = *(const float4*)&As[kk][ty * 4];
            a[0]=t0.x; a[1]=t0.y; a[2]=t0.z; a[3]=t0.w;
            float4 u0 = *(const float4*)&Bs[kk][tx * 8];
            float4 u1 = *(const float4*)&Bs[kk][tx * 8 + 4];
            bvv[0]=u0.x; bvv[1]=u0.y; bvv[2]=u0.z; bvv[3]=u0.w;
            bvv[4]=u1.x; bvv[5]=u1.y; bvv[6]=u1.z; bvv[7]=u1.w;
            #pragma unroll
            for (int i = 0; i < 4; i++)
                #pragma unroll
                for (int j = 0; j < 8; j++)
                    acc[i][j] += a[i] * bvv[j];
        }
    }
    #pragma unroll
    for (int i = 0; i < 4; i++) {
        int row = ty * 4 + i;
        float bias = (row < 32) ? bq[row] : bk[row - 32];
        float* dst = ((row < 32) ? (g_q + (b * C8 + row) * NP)
                                 : (g_k + (b * C8 + row - 32) * NP)) + p0 + tx * 8;
        *(float4*)dst       = make_float4(acc[i][0]+bias, acc[i][1]+bias, acc[i][2]+bias, acc[i][3]+bias);
        *(float4*)(dst + 4) = make_float4(acc[i][4]+bias, acc[i][5]+bias, acc[i][6]+bias, acc[i][7]+bias);
    }
}

// ---------------- row softmax over 4096, bf16 in place (u32-vectorized) ----------------
__global__ __launch_bounds__(256) void softmax_kernel() {
    size_t row = blockIdx.x;
    uint32_t* ptr = (uint32_t*)(g_attnh + row * (size_t)NP);   // 2048 u32
    int tid = threadIdx.x;
    float vals[16];
    float m = -1e30f;
    #pragma unroll
    for (int s = 0; s < 8; s++) {
        uint32_t u = ptr[tid + s * 256];
        float lo = __bfloat162float(__ushort_as_bfloat16((unsigned short)(u & 0xffff)));
        float hi = __bfloat162float(__ushort_as_bfloat16((unsigned short)(u >> 16)));
        vals[2 * s] = lo; vals[2 * s + 1] = hi;
        m = fmaxf(m, fmaxf(lo, hi));
    }
    #pragma unroll
    for (int o = 16; o; o >>= 1) m = fmaxf(m, __shfl_xor_sync(0xffffffffu, m, o));
    __shared__ float shm[8], shs[8];
    int w = tid >> 5, l = tid & 31;
    if (l == 0) shm[w] = m;
    __syncthreads();
    m = fmaxf(fmaxf(fmaxf(shm[0], shm[1]), fmaxf(shm[2], shm[3])),
              fmaxf(fmaxf(shm[4], shm[5]), fmaxf(shm[6], shm[7])));
    float sum = 0.f;
    #pragma unroll
    for (int s = 0; s < 16; s++) {
        vals[s] = __expf(vals[s] - m);
        sum += vals[s];
    }
    #pragma unroll
    for (int o = 16; o; o >>= 1) sum += __shfl_xor_sync(0xffffffffu, sum, o);
    if (l == 0) shs[w] = sum;
    __syncthreads();
    sum = shs[0] + shs[1] + shs[2] + shs[3] + shs[4] + shs[5] + shs[6] + shs[7];
    float inv = 1.0f / sum;
    #pragma unroll
    for (int s = 0; s < 8; s++)
        ptr[tid + s * 256] = pbf2(vals[2 * s] * inv, vals[2 * s + 1] * inv);
}

// ---------------- launcher ----------------
extern "C" void kernel_launch(void* const* d_in, const int* in_sizes, int n_in,
                              void* d_out, int out_size) {
    const float* x     = (const float*)d_in[0];
    const float* w1    = (const float*)d_in[1];
    const float* b1    = (const float*)d_in[2];
    const float* w2    = (const float*)d_in[3];
    const float* b2    = (const float*)d_in[4];
    const float* wq    = (const float*)d_in[5];
    const float* bq    = (const float*)d_in[6];
    const float* wk    = (const float*)d_in[7];
    const float* bk    = (const float*)d_in[8];
    const float* wv    = (const float*)d_in[9];
    const float* bv    = (const float*)d_in[10];
    const float* gamma = (const float*)d_in[11];
    float* out = (float*)d_out;

    cudaFuncSetAttribute(tc_gemm<0, KCONV>, cudaFuncAttributeMaxDynamicSharedMemorySize, SMEM_DYN);
    cudaFuncSetAttribute(tc_gemm<1, CC>,    cudaFuncAttributeMaxDynamicSharedMemorySize, SMEM_DYN);
    cudaFuncSetAttribute(o_gemm_bf16,       cudaFuncAttributeMaxDynamicSharedMemorySize, OSMEM);

    dim3 g128(NP / 128, CC / 128, BB);   // (32,2,2)

    // conv block
    pad_kernel<<<BB * CC, 256>>>(x);
    wtrans_kernel<<<CC, 256>>>(w1);
    tc_gemm<0, KCONV><<<g128, 256, SMEM_DYN>>>(nullptr, b1);
    stats_pad_kernel<<<BB * CC, 256>>>();          // fused stats + instnorm+relu+pad
    wtrans_kernel<<<CC, 256>>>(w2);
    tc_gemm<0, KCONV><<<g128, 256, SMEM_DYN>>>(nullptr, b2);
    stats_norm_kernel<<<BB * CC, 256>>>(x);        // fused stats + residual add

    // attention
    qk_gemm<<<dim3(NP / 128, 1, BB), 256>>>(wq, bq, wk, bk);
    tc_gemm<1, CC><<<g128, 256, SMEM_DYN>>>(wv, bv);
    energy_tc<<<dim3(NP / 128, NP / 128, BB), 256>>>();
    softmax_kernel<<<BB * NP, 256>>>();
    o_gemm_bf16<<<g128, 256, OSMEM>>>(gamma, out);
}

// round 11
// speedup vs baseline: 1.2768x; 1.0448x over previous
#include <cuda_runtime.h>
#include <cuda_bf16.h>
#include <math.h>
#include <stdint.h>

#define EPSV 1e-5f
#define BB 2
#define CC 256
#define C8 32
#define NP 4096          // 16*16*16 positions
#define PADN 5832        // 18*18*18
#define KCONV (CC*27)    // 6912

// ---------------- scratch ----------------
__device__ float g_pad[BB*CC*PADN];
__device__ float g_y[BB*CC*NP];
__device__ float g_out[BB*CC*NP];
__device__ float g_q[BB*C8*NP];
__device__ float g_k[BB*C8*NP];
__device__ __nv_bfloat16 g_vh[BB*CC*NP];             // bf16 V (only consumer is bf16 o-GEMM)
__device__ __nv_bfloat16 g_attnh[(size_t)BB*NP*NP];  // bf16 energies -> softmaxed in place
__device__ float g_wt[CC*KCONV];     // transposed conv1 weights: wt[co][tap*256+cin]
__device__ float g_wt2[CC*KCONV];    // transposed conv2 weights

// padded-offset per conv tap (strides 324/18/1)
__constant__ int c_doff[27] = {
  -343,-342,-341,-325,-324,-323,-307,-306,-305,
   -19, -18, -17,  -1,   0,   1,  17,  18,  19,
   305, 306, 307, 323, 324, 325, 341, 342, 343};

// ---------------- helpers ----------------
__device__ __forceinline__ float tf32r(float x) {
    uint32_t u;
    asm("cvt.rna.tf32.f32 %0, %1;" : "=r"(u) : "f"(x));
    return __uint_as_float(u);
}
__device__ __forceinline__ void mma_tf32(float (&d)[4], const float4 &a, const float2 &b) {
    asm volatile(
        "mma.sync.aligned.m16n8k8.row.col.f32.tf32.tf32.f32 "
        "{%0,%1,%2,%3}, {%4,%5,%6,%7}, {%8,%9}, {%0,%1,%2,%3};\n"
        : "+f"(d[0]), "+f"(d[1]), "+f"(d[2]), "+f"(d[3])
        : "r"(__float_as_uint(a.x)), "r"(__float_as_uint(a.y)),
          "r"(__float_as_uint(a.z)), "r"(__float_as_uint(a.w)),
          "r"(__float_as_uint(b.x)), "r"(__float_as_uint(b.y)));
}
__device__ __forceinline__ void mma_bf16(float (&d)[4], const uint4 &a, const uint2 &b) {
    asm volatile(
        "mma.sync.aligned.m16n8k16.row.col.f32.bf16.bf16.f32 "
        "{%0,%1,%2,%3}, {%4,%5,%6,%7}, {%8,%9}, {%0,%1,%2,%3};\n"
        : "+f"(d[0]), "+f"(d[1]), "+f"(d[2]), "+f"(d[3])
        : "r"(a.x), "r"(a.y), "r"(a.z), "r"(a.w), "r"(b.x), "r"(b.y));
}
__device__ __forceinline__ uint32_t pbf2(float lo, float hi) {
    return (uint32_t)__bfloat16_as_ushort(__float2bfloat16_rn(lo))
         | ((uint32_t)__bfloat16_as_ushort(__float2bfloat16_rn(hi)) << 16);
}

// ---------------- weight transpose (both weights in one launch) ----------------
__global__ __launch_bounds__(256) void wtrans_kernel(const float* __restrict__ w1,
                                                     const float* __restrict__ w2) {
    int co = blockIdx.x;
    int cin = threadIdx.x;
    const float* w   = blockIdx.y ? w2 : w1;
    float*       wt  = blockIdx.y ? g_wt2 : g_wt;
    const float* src = w + (size_t)co * KCONV + (size_t)cin * 27;
    float v[27];
    #pragma unroll
    for (int t = 0; t < 27; t++) v[t] = src[t];
    float* dst = wt + (size_t)co * KCONV + cin;
    #pragma unroll
    for (int t = 0; t < 27; t++) dst[t * 256] = v[t];
}

// ---------------- pad kernel: x -> g_pad (zero-fill then direct interior map) ----------------
__global__ void pad_kernel(const float* __restrict__ x) {
    int bc = blockIdx.x;
    const float* src = x + (size_t)bc * NP;
    float* dst = g_pad + (size_t)bc * PADN;
    int tid = threadIdx.x;
    // coalesced zero of all 5832 floats (1458 float4)
    float4 z4 = make_float4(0.f, 0.f, 0.f, 0.f);
    #pragma unroll
    for (int s = 0; s < 6; s++) {
        int i = tid + s * 256;
        if (i < PADN / 4) *(float4*)(dst + i * 4) = z4;
    }
    __syncthreads();
    // interior: 4096 elements, shifts only
    #pragma unroll
    for (int s = 0; s < 16; s++) {
        int idx = tid + s * 256;
        int zc = idx & 15, yc = (idx >> 4) & 15, xc = idx >> 8;
        dst[(xc + 1) * 324 + (yc + 1) * 18 + (zc + 1)] = src[idx];
    }
}

// ---------------- block-wide mean/rstd of g_y[bc] (broadcast via smem) ----------------
__device__ __forceinline__ void block_stats(const float* __restrict__ src,
                                            float& mean, float& rstd) {
    float s = 0.f, ss = 0.f;
    for (int i = threadIdx.x; i < NP; i += 256) {
        float v = src[i]; s += v; ss += v * v;
    }
    #pragma unroll
    for (int o = 16; o; o >>= 1) {
        s  += __shfl_down_sync(0xffffffffu, s, o);
        ss += __shfl_down_sync(0xffffffffu, ss, o);
    }
    __shared__ float sh_s[8], sh_ss[8], sh_m, sh_r;
    int w = threadIdx.x >> 5, l = threadIdx.x & 31;
    if (l == 0) { sh_s[w] = s; sh_ss[w] = ss; }
    __syncthreads();
    if (threadIdx.x == 0) {
        float S = 0.f, SS = 0.f;
        #pragma unroll
        for (int i = 0; i < 8; i++) { S += sh_s[i]; SS += sh_ss[i]; }
        float m = S * (1.0f / NP);
        float var = SS * (1.0f / NP) - m * m;
        sh_m = m;
        sh_r = rsqrtf(var + EPSV);
    }
    __syncthreads();
    mean = sh_m; rstd = sh_r;
}

// ---------------- fused: stats(g_y[bc]) then instnorm+relu -> g_pad (zero+interior) ----------------
__global__ void stats_pad_kernel() {
    int bc = blockIdx.x;
    const float* src = g_y + (size_t)bc * NP;
    float m, r;
    block_stats(src, m, r);
    float* dst = g_pad + (size_t)bc * PADN;
    int tid = threadIdx.x;
    float4 z4 = make_float4(0.f, 0.f, 0.f, 0.f);
    #pragma unroll
    for (int s = 0; s < 6; s++) {
        int i = tid + s * 256;
        if (i < PADN / 4) *(float4*)(dst + i * 4) = z4;
    }
    __syncthreads();
    #pragma unroll
    for (int s = 0; s < 16; s++) {
        int idx = tid + s * 256;
        int zc = idx & 15, yc = (idx >> 4) & 15, xc = idx >> 8;
        dst[(xc + 1) * 324 + (yc + 1) * 18 + (zc + 1)] = fmaxf((src[idx] - m) * r, 0.f);
    }
}

// ---------------- fused: stats(g_y[bc]) then g_out = x + instnorm(g_y) ----------------
__global__ void stats_norm_kernel(const float* __restrict__ x) {
    int bc = blockIdx.x;
    const float* src = g_y + (size_t)bc * NP;
    float m, r;
    block_stats(src, m, r);
    const float* xb = x + (size_t)bc * NP;
    float* dst = g_out + (size_t)bc * NP;
    for (int i = threadIdx.x; i < NP; i += 256)
        dst[i] = xb[i] + (src[i] - m) * r;
}

// ============================================================================
// Pipelined mma.sync tf32 GEMM, 128x128 tile, k-step 32, 2-stage smem.
// MODE 0 (CONV):  A=wt[co][(tap,cin)], B=im2col(g_pad), dst=g_y fp32 (+bias)
// MODE 1 (VPROJ): A=Aext(wv),          B=g_out[c][p],   dst=g_vh bf16 (+bias)
// ============================================================================
#define STG_FLOATS 8320
#define SMEM_DYN (2 * STG_FLOATS * 4)

template<int MODE, int KTOT, int CONVSEL>
__global__ __launch_bounds__(256, 1)
void tc_gemm(const float* __restrict__ Aext, const float* __restrict__ bias) {
    constexpr int NCH = KTOT / 32;
    extern __shared__ float sm[];
    const int tid = threadIdx.x, wid = tid >> 5, lane = tid & 31;
    const int bb = blockIdx.z;
    const int m0 = blockIdx.y * 128, n0 = blockIdx.x * 128;

    // ---- A loader ----
    const int amt = tid >> 5;
    const int arg = (tid >> 2) & 7;
    const int akb = tid & 3;
    const float* aptr0;
    const float* aptr1;
    {
        int m = m0 + amt * 16 + arg;
        const float* base = (MODE == 0) ? (CONVSEL ? g_wt2 : g_wt) : Aext;
        aptr0 = base + (size_t)m * KTOT + akb * 8;
        aptr1 = base + (size_t)(m + 8) * KTOT + akb * 8;
    }

    // ---- B loader ----
    const int bn = tid >> 1;
    const int bkh = (tid & 1) * 2;
    int pofs = 0;
    const float* bbase = nullptr;
    if (MODE == 0) {
        int p = n0 + bn;
        int pz = p & 15, py = (p >> 4) & 15, px = p >> 8;
        pofs = (px + 1) * 324 + (py + 1) * 18 + (pz + 1);
        bbase = g_pad + (size_t)bb * CC * PADN;
    } else {
        bbase = g_out + (size_t)bb * CC * NP + n0 + bn;
    }

    float ar0[8], ar1[8], br[16];

    #define LOAD_A(ch_) do { \
        *(float4*)(ar0)     = *(const float4*)(aptr0 + (size_t)(ch_) * 32); \
        *(float4*)(ar0 + 4) = *(const float4*)(aptr0 + (size_t)(ch_) * 32 + 4); \
        *(float4*)(ar1)     = *(const float4*)(aptr1 + (size_t)(ch_) * 32); \
        *(float4*)(ar1 + 4) = *(const float4*)(aptr1 + (size_t)(ch_) * 32 + 4); \
    } while (0)

    #define LOAD_B(ch_) do { \
        if (MODE == 0) { \
            _Pragma("unroll") \
            for (int t = 0; t < 2; t++) { \
                _Pragma("unroll") \
                for (int c = 0; c < 8; c++) { \
                    int k = (ch_) * 32 + (bkh + t) * 8 + c; \
                    int tap = k >> 8, cin = k & 255; \
                    br[t * 8 + c] = bbase[(size_t)cin * PADN + c_doff[tap] + pofs]; \
                } \
            } \
        } else { \
            _Pragma("unroll") \
            for (int t = 0; t < 2; t++) { \
                _Pragma("unroll") \
                for (int c = 0; c < 8; c++) { \
                    int k = (ch_) * 32 + (bkh + t) * 8 + c; \
                    br[t * 8 + c] = bbase[(size_t)k * NP]; \
                } \
            } \
        } \
    } while (0)

    #define STORE_AB(stg_) do { \
        float* As_ = sm + (stg_) * STG_FLOATS + amt * 512 + akb * 128 + arg * 16; \
        _Pragma("unroll") \
        for (int c = 0; c < 4; c++) { \
            *(float4*)(As_ + c * 4) = make_float4( \
                tf32r(ar0[c]), tf32r(ar1[c]), tf32r(ar0[c + 4]), tf32r(ar1[c + 4])); \
        } \
        float* Bs_ = sm + (stg_) * STG_FLOATS + 4096 + (bn >> 3) * 264 + (bn & 7) * 8; \
        _Pragma("unroll") \
        for (int t = 0; t < 2; t++) { \
            int kbb = bkh + t; \
            _Pragma("unroll") \
            for (int c = 0; c < 4; c++) { \
                *(float2*)(Bs_ + kbb * 64 + c * 2) = \
                    make_float2(tf32r(br[t * 8 + c]), tf32r(br[t * 8 + c + 4])); \
            } \
        } \
    } while (0)

    const int wm = wid & 1, wn = wid >> 1;
    float acc[4][4][4];
    #pragma unroll
    for (int i = 0; i < 4; i++)
        #pragma unroll
        for (int j = 0; j < 4; j++)
            #pragma unroll
            for (int k = 0; k < 4; k++) acc[i][j][k] = 0.f;

    LOAD_A(0); LOAD_B(0);
    STORE_AB(0);
    LOAD_A(1); LOAD_B(1);
    __syncthreads();

    for (int ch = 0; ch < NCH; ch++) {
        int cur = ch & 1;
        if (ch + 1 < NCH) STORE_AB(cur ^ 1);
        if (ch + 2 < NCH) { LOAD_A(ch + 2); LOAD_B(ch + 2); }

        const float* As_ = sm + cur * STG_FLOATS;
        const float* Bs_ = As_ + 4096;
        #pragma unroll
        for (int kb = 0; kb < 4; kb++) {
            float4 af[4]; float2 bf[4];
            #pragma unroll
            for (int mt = 0; mt < 4; mt++)
                af[mt] = *(const float4*)(As_ + (wm * 4 + mt) * 512 + kb * 128 + lane * 4);
            #pragma unroll
            for (int nt = 0; nt < 4; nt++)
                bf[nt] = *(const float2*)(Bs_ + (wn * 4 + nt) * 264 + kb * 64 + lane * 2);
            #pragma unroll
            for (int mt = 0; mt < 4; mt++)
                #pragma unroll
                for (int nt = 0; nt < 4; nt++)
                    mma_tf32(acc[mt][nt], af[mt], bf[nt]);
        }
        __syncthreads();
    }

    #undef LOAD_A
    #undef LOAD_B
    #undef STORE_AB

    const int g = lane >> 2, tg = lane & 3;
    #pragma unroll
    for (int mt = 0; mt < 4; mt++) {
        int m = m0 + wm * 64 + mt * 16 + g;
        float bs0 = bias[m], bs1 = bias[m + 8];
        #pragma unroll
        for (int nt = 0; nt < 4; nt++) {
            int n = n0 + wn * 32 + nt * 8 + tg * 2;
            size_t base0 = (size_t)(bb * CC + m) * NP + n;
            size_t base1 = base0 + (size_t)8 * NP;
            if (MODE == 0) {
                *(float2*)(g_y + base0) = make_float2(acc[mt][nt][0] + bs0, acc[mt][nt][1] + bs0);
                *(float2*)(g_y + base1) = make_float2(acc[mt][nt][2] + bs1, acc[mt][nt][3] + bs1);
            } else {
                *(uint32_t*)(g_vh + base0) = pbf2(acc[mt][nt][0] + bs0, acc[mt][nt][1] + bs0);
                *(uint32_t*)(g_vh + base1) = pbf2(acc[mt][nt][2] + bs1, acc[mt][nt][3] + bs1);
            }
        }
    }
}

// ============================================================================
// o-GEMM, bf16 m16n8k16: o[c,i] = sum_j v[c,j]*attnh[i,j]; dout = gamma*o+g_out
// A (=g_vh) is already bf16 -> loader reads u32 pairs, OSTORE is a permute.
// ============================================================================
#define OA_U32 2048
#define OB_U32 (16*136)
#define OSTG_U32 (OA_U32 + OB_U32)
#define OSMEM (2 * OSTG_U32 * 4)

__global__ __launch_bounds__(256, 1)
void o_gemm_bf16(const float* __restrict__ gamma, float* __restrict__ dout) {
    extern __shared__ uint32_t smu[];
    const int tid = threadIdx.x, wid = tid >> 5, lane = tid & 31;
    const int bb = blockIdx.z, m0 = blockIdx.y * 128, i0 = blockIdx.x * 128;
    const int wm = wid & 1, wn = wid >> 1;

    const uint32_t *av0 = nullptr, *av1 = nullptr;
    uint32_t aoff = 0;
    if (tid < 128) {
        int rpi = tid >> 1, akb = tid & 1;
        int mt = rpi >> 3, rp = rpi & 7;
        int m = m0 + mt * 16 + rp;
        av0 = (const uint32_t*)(g_vh + (size_t)(bb * CC + m) * NP) + akb * 8;
        av1 = av0 + (size_t)4 * NP;    // +8 rows of NP bf16 = 4*NP u32
        aoff = mt * 256 + akb * 128 + rp * 16;
    }
    const int bn = tid >> 1, bkb = tid & 1;
    const __nv_bfloat16* bptr = g_attnh + ((size_t)bb * NP + i0 + bn) * NP + bkb * 16;
    const uint32_t boff = OA_U32 + (bn >> 3) * 136 + bkb * 68 + (bn & 7) * 8;

    uint32_t a0u[8], a1u[8];
    uint32_t brg[8];

    #define OLOAD(ch_) do { \
        if (tid < 128) { \
            *(uint4*)(a0u)     = *(const uint4*)(av0 + (size_t)(ch_) * 16); \
            *(uint4*)(a0u + 4) = *(const uint4*)(av0 + (size_t)(ch_) * 16 + 4); \
            *(uint4*)(a1u)     = *(const uint4*)(av1 + (size_t)(ch_) * 16); \
            *(uint4*)(a1u + 4) = *(const uint4*)(av1 + (size_t)(ch_) * 16 + 4); \
        } \
        *(uint4*)(brg)     = *(const uint4*)(bptr + (size_t)(ch_) * 32); \
        *(uint4*)(brg + 4) = *(const uint4*)(bptr + (size_t)(ch_) * 32 + 8); \
    } while (0)

    #define OSTORE(stg_) do { \
        uint32_t* s_ = smu + (stg_) * OSTG_U32; \
        if (tid < 128) { \
            _Pragma("unroll") \
            for (int t = 0; t < 4; t++) { \
                *(uint4*)(s_ + aoff + t * 4) = \
                    make_uint4(a0u[t], a1u[t], a0u[t + 4], a1u[t + 4]); \
            } \
        } \
        _Pragma("unroll") \
        for (int t = 0; t < 4; t++) \
            *(uint2*)(s_ + boff + t * 2) = make_uint2(brg[t], brg[t + 4]); \
    } while (0)

    float acc[4][4][4];
    #pragma unroll
    for (int i = 0; i < 4; i++)
        #pragma unroll
        for (int j = 0; j < 4; j++)
            #pragma unroll
            for (int k = 0; k < 4; k++) acc[i][j][k] = 0.f;

    OLOAD(0); OSTORE(0); OLOAD(1);
    __syncthreads();

    constexpr int NCH = NP / 32;   // 128
    for (int ch = 0; ch < NCH; ch++) {
        int cur = ch & 1;
        if (ch + 1 < NCH) OSTORE(cur ^ 1);
        if (ch + 2 < NCH) OLOAD(ch + 2);

        const uint32_t* s_ = smu + cur * OSTG_U32;
        #pragma unroll
        for (int kb = 0; kb < 2; kb++) {
            uint4 af[4]; uint2 bf[4];
            #pragma unroll
            for (int mt = 0; mt < 4; mt++)
                af[mt] = *(const uint4*)(s_ + (wm * 4 + mt) * 256 + kb * 128 + lane * 4);
            #pragma unroll
            for (int nt = 0; nt < 4; nt++)
                bf[nt] = *(const uint2*)(s_ + OA_U32 + (wn * 4 + nt) * 136 + kb * 68 + lane * 2);
            #pragma unroll
            for (int mt = 0; mt < 4; mt++)
                #pragma unroll
                for (int nt = 0; nt < 4; nt++)
                    mma_bf16(acc[mt][nt], af[mt], bf[nt]);
        }
        __syncthreads();
    }

    #undef OLOAD
    #undef OSTORE

    const int g = lane >> 2, tg = lane & 3;
    const float gm = gamma[0];
    #pragma unroll
    for (int mt = 0; mt < 4; mt++) {
        int m = m0 + wm * 64 + mt * 16 + g;
        #pragma unroll
        for (int nt = 0; nt < 4; nt++) {
            int n = i0 + wn * 32 + nt * 8 + tg * 2;
            size_t base0 = (size_t)(bb * CC + m) * NP + n;
            size_t base1 = base0 + (size_t)8 * NP;
            const float* r0 = g_out + base0;
            const float* r1 = g_out + base1;
            *(float2*)(dout + base0) =
                make_float2(gm * acc[mt][nt][0] + r0[0], gm * acc[mt][nt][1] + r0[1]);
            *(float2*)(dout + base1) =
                make_float2(gm * acc[mt][nt][2] + r1[0], gm * acc[mt][nt][3] + r1[1]);
        }
    }
}

// ---------------- energy -> bf16 g_attnh: energy[b,i,j] = sum_c q[b,c,i]*k[b,c,j] ----------------
__global__ __launch_bounds__(256) void energy_tc() {
    __shared__ float As[8][2][32][4];
    __shared__ float Bs[16][2][32][2];
    int tid = threadIdx.x, b = blockIdx.z;
    int i0 = blockIdx.y * 128, j0 = blockIdx.x * 128;

    int cl = tid >> 4, ig = tid & 15;
    int ckblk = cl >> 3, ckc = cl & 7;

    int wid = tid >> 5, lane = tid & 31;
    int wm = wid & 1, wn = wid >> 1;

    float acc[4][4][4];
    #pragma unroll
    for (int i = 0; i < 4; i++)
        #pragma unroll
        for (int j = 0; j < 4; j++)
            #pragma unroll
            for (int k = 0; k < 4; k++) acc[i][j][k] = 0.f;

    #pragma unroll
    for (int it = 0; it < 2; ++it) {
        int c = it * 16 + cl;
        const float* qsrc = g_q + (size_t)(b * C8 + c) * NP + i0 + ig * 8;
        const float* ksrc = g_k + (size_t)(b * C8 + c) * NP + j0 + ig * 8;
        float4 q0 = *(const float4*)qsrc, q1 = *(const float4*)(qsrc + 4);
        float4 k0 = *(const float4*)ksrc, k1 = *(const float4*)(ksrc + 4);

        __syncthreads();
        {
            float qv[8] = {q0.x, q0.y, q0.z, q0.w, q1.x, q1.y, q1.z, q1.w};
            #pragma unroll
            for (int ii = 0; ii < 8; ii++) {
                int r = ig * 8 + ii;
                int mtile = r >> 4, rr = r & 15;
                As[mtile][ckblk][(rr & 7) * 4 + (ckc & 3)][(rr >> 3) + ((ckc >> 2) << 1)] = tf32r(qv[ii]);
            }
            float kv[8] = {k0.x, k0.y, k0.z, k0.w, k1.x, k1.y, k1.z, k1.w};
            #pragma unroll
            for (int nn = 0; nn < 8; nn++)
                Bs[ig][ckblk][nn * 4 + (ckc & 3)][ckc >> 2] = tf32r(kv[nn]);
        }
        __syncthreads();

        #pragma unroll
        for (int kb = 0; kb < 2; kb++) {
            float4 af[4]; float2 bf[4];
            #pragma unroll
            for (int mt = 0; mt < 4; mt++) af[mt] = *(const float4*)As[wm * 4 + mt][kb][lane];
            #pragma unroll
            for (int nt = 0; nt < 4; nt++) bf[nt] = *(const float2*)Bs[wn * 4 + nt][kb][lane];
            #pragma unroll
            for (int mt = 0; mt < 4; mt++)
                #pragma unroll
                for (int nt = 0; nt < 4; nt++)
                    mma_tf32(acc[mt][nt], af[mt], bf[nt]);
        }
    }

    int g = lane >> 2, tg = lane & 3;
    #pragma unroll
    for (int mt = 0; mt < 4; mt++) {
        int m = i0 + wm * 64 + mt * 16 + g;
        #pragma unroll
        for (int nt = 0; nt < 4; nt++) {
            int n = j0 + wn * 32 + nt * 8 + tg * 2;
            __nv_bfloat16* d0 = g_attnh + ((size_t)b * NP + m) * NP + n;
            *(uint32_t*)d0 = pbf2(acc[mt][nt][0], acc[mt][nt][1]);
            *(uint32_t*)(d0 + (size_t)8 * NP) = pbf2(acc[mt][nt][2], acc[mt][nt][3]);
        }
    }
}

// ---------------- q and k projections fused (FFMA, small) ----------------
__global__ __launch_bounds__(256) void qk_gemm(const float* __restrict__ wq, const float* __restrict__ bq,
                                               const float* __restrict__ wk, const float* __restrict__ bk) {
    __shared__ float As[8][64];
    __shared__ float Bs[8][128];
    int tid = threadIdx.x, b = blockIdx.z;
    int p0 = blockIdx.x * 128;
    int arow = tid >> 2;
    int acol = (tid & 3) * 2;
    const float* ap = ((arow < 32) ? (wq + arow * CC) : (wk + (arow - 32) * CC)) + acol;
    int brow = tid >> 5, bcol = (tid & 31) * 4;
    const float* bp = g_out + (b * CC + brow) * NP + p0 + bcol;
    int ty = tid >> 4, tx = tid & 15;
    float acc[4][8];
    #pragma unroll
    for (int i = 0; i < 4; i++)
        #pragma unroll
        for (int j = 0; j < 8; j++) acc[i][j] = 0.f;

    for (int it = 0; it < CC / 8; ++it) {
        float2 av = *(const float2*)(ap + it * 8);
        float4 bv = *(const float4*)(bp + (size_t)it * 8 * NP);
        __syncthreads();
        As[acol + 0][arow] = av.x;
        As[acol + 1][arow] = av.y;
        *(float4*)&Bs[brow][bcol] = bv;
        __syncthreads();
        #pragma unroll
        for (int kk = 0; kk < 8; kk++) {
            float a[4], bvv[8];
            float4 t0 = *(const float4*)&As[kk][ty * 4];
            a[0]=t0.x; a[1]=t0.y; a[2]=t0.z; a[3]=t0.w;
            float4 u0 = *(const float4*)&Bs[kk][tx * 8];
            float4 u1 = *(const float4*)&Bs[kk][tx * 8 + 4];
            bvv[0]=u0.x; bvv[1]=u0.y; bvv[2]=u0.z; bvv[3]=u0.w;
            bvv[4]=u1.x; bvv[5]=u1.y; bvv[6]=u1.z; bvv[7]=u1.w;
            #pragma unroll
            for (int i = 0; i < 4; i++)
                #pragma unroll
                for (int j = 0; j < 8; j++)
                    acc[i][j] += a[i] * bvv[j];
        }
    }
    #pragma unroll
    for (int i = 0; i < 4; i++) {
        int row = ty * 4 + i;
        float bias = (row < 32) ? bq[row] : bk[row - 32];
        float* dst = ((row < 32) ? (g_q + (b * C8 + row) * NP)
                                 : (g_k + (b * C8 + row - 32) * NP)) + p0 + tx * 8;
        *(float4*)dst       = make_float4(acc[i][0]+bias, acc[i][1]+bias, acc[i][2]+bias, acc[i][3]+bias);
        *(float4*)(dst + 4) = make_float4(acc[i][4]+bias, acc[i][5]+bias, acc[i][6]+bias, acc[i][7]+bias);
    }
}

// ---------------- row softmax over 4096, bf16 in place (u32-vectorized) ----------------
__global__ __launch_bounds__(256) void softmax_kernel() {
    size_t row = blockIdx.x;
    uint32_t* ptr = (uint32_t*)(g_attnh + row * (size_t)NP);   // 2048 u32
    int tid = threadIdx.x;
    float vals[16];
    float m = -1e30f;
    #pragma unroll
    for (int s = 0; s < 8; s++) {
        uint32_t u = ptr[tid + s * 256];
        float lo = __bfloat162float(__ushort_as_bfloat16((unsigned short)(u & 0xffff)));
        float hi = __bfloat162float(__ushort_as_bfloat16((unsigned short)(u >> 16)));
        vals[2 * s] = lo; vals[2 * s + 1] = hi;
        m = fmaxf(m, fmaxf(lo, hi));
    }
    #pragma unroll
    for (int o = 16; o; o >>= 1) m = fmaxf(m, __shfl_xor_sync(0xffffffffu, m, o));
    __shared__ float shm[8], shs[8];
    int w = tid >> 5, l = tid & 31;
    if (l == 0) shm[w] = m;
    __syncthreads();
    m = fmaxf(fmaxf(fmaxf(shm[0], shm[1]), fmaxf(shm[2], shm[3])),
              fmaxf(fmaxf(shm[4], shm[5]), fmaxf(shm[6], shm[7])));
    float sum = 0.f;
    #pragma unroll
    for (int s = 0; s < 16; s++) {
        vals[s] = __expf(vals[s] - m);
        sum += vals[s];
    }
    #pragma unroll
    for (int o = 16; o; o >>= 1) sum += __shfl_xor_sync(0xffffffffu, sum, o);
    if (l == 0) shs[w] = sum;
    __syncthreads();
    sum = shs[0] + shs[1] + shs[2] + shs[3] + shs[4] + shs[5] + shs[6] + shs[7];
    float inv = 1.0f / sum;
    #pragma unroll
    for (int s = 0; s < 8; s++)
        ptr[tid + s * 256] = pbf2(vals[2 * s] * inv, vals[2 * s + 1] * inv);
}

// ---------------- launcher ----------------
extern "C" void kernel_launch(void* const* d_in, const int* in_sizes, int n_in,
                              void* d_out, int out_size) {
    const float* x     = (const float*)d_in[0];
    const float* w1    = (const float*)d_in[1];
    const float* b1    = (const float*)d_in[2];
    const float* w2    = (const float*)d_in[3];
    const float* b2    = (const float*)d_in[4];
    const float* wq    = (const float*)d_in[5];
    const float* bq    = (const float*)d_in[6];
    const float* wk    = (const float*)d_in[7];
    const float* bk    = (const float*)d_in[8];
    const float* wv    = (const float*)d_in[9];
    const float* bv    = (const float*)d_in[10];
    const float* gamma = (const float*)d_in[11];
    float* out = (float*)d_out;

    cudaFuncSetAttribute(tc_gemm<0, KCONV, 0>, cudaFuncAttributeMaxDynamicSharedMemorySize, SMEM_DYN);
    cudaFuncSetAttribute(tc_gemm<0, KCONV, 1>, cudaFuncAttributeMaxDynamicSharedMemorySize, SMEM_DYN);
    cudaFuncSetAttribute(tc_gemm<1, CC, 0>,    cudaFuncAttributeMaxDynamicSharedMemorySize, SMEM_DYN);
    cudaFuncSetAttribute(o_gemm_bf16,          cudaFuncAttributeMaxDynamicSharedMemorySize, OSMEM);

    dim3 g128(NP / 128, CC / 128, BB);   // (32,2,2)

    // conv block
    wtrans_kernel<<<dim3(CC, 2), 256>>>(w1, w2);   // both weight transposes at once
    pad_kernel<<<BB * CC, 256>>>(x);
    tc_gemm<0, KCONV, 0><<<g128, 256, SMEM_DYN>>>(nullptr, b1);
    stats_pad_kernel<<<BB * CC, 256>>>();          // fused stats + instnorm+relu+pad
    tc_gemm<0, KCONV, 1><<<g128, 256, SMEM_DYN>>>(nullptr, b2);
    stats_norm_kernel<<<BB * CC, 256>>>(x);        // fused stats + residual add

    // attention
    qk_gemm<<<dim3(NP / 128, 1, BB), 256>>>(wq, bq, wk, bk);
    tc_gemm<1, CC, 0><<<g128, 256, SMEM_DYN>>>(wv, bv);   // V proj -> bf16 g_vh
    energy_tc<<<dim3(NP / 128, NP / 128, BB), 256>>>();
    softmax_kernel<<<BB * NP, 256>>>();
    o_gemm_bf16<<<g128, 256, OSMEM>>>(gamma, out);
}

// round 12
// speedup vs baseline: 1.3078x; 1.0243x over previous
#include <cuda_runtime.h>
#include <cuda_bf16.h>
#include <math.h>
#include <stdint.h>

#define EPSV 1e-5f
#define BB 2
#define CC 256
#define C8 32
#define NP 4096          // 16*16*16 positions
#define PADN 5832        // 18*18*18
#define KCONV (CC*27)    // 6912

// ---------------- scratch ----------------
__device__ float g_pad[BB*CC*PADN];
__device__ float g_y[BB*CC*NP];
__device__ float g_out[BB*CC*NP];
__device__ float g_q[BB*C8*NP];
__device__ float g_k[BB*C8*NP];
__device__ __nv_bfloat16 g_vh[BB*CC*NP];             // bf16 V (only consumer is bf16 o-GEMM)
__device__ __nv_bfloat16 g_attnh[(size_t)BB*NP*NP];  // bf16 energies -> softmaxed in place
__device__ float g_wt[CC*KCONV];     // transposed conv1 weights: wt[co][tap*256+cin]
__device__ float g_wt2[CC*KCONV];    // transposed conv2 weights

// padded-offset per conv tap (strides 324/18/1)
__constant__ int c_doff[27] = {
  -343,-342,-341,-325,-324,-323,-307,-306,-305,
   -19, -18, -17,  -1,   0,   1,  17,  18,  19,
   305, 306, 307, 323, 324, 325, 341, 342, 343};

// ---------------- helpers ----------------
__device__ __forceinline__ float tf32r(float x) {
    uint32_t u;
    asm("cvt.rna.tf32.f32 %0, %1;" : "=r"(u) : "f"(x));
    return __uint_as_float(u);
}
__device__ __forceinline__ void mma_tf32(float (&d)[4], const float4 &a, const float2 &b) {
    asm volatile(
        "mma.sync.aligned.m16n8k8.row.col.f32.tf32.tf32.f32 "
        "{%0,%1,%2,%3}, {%4,%5,%6,%7}, {%8,%9}, {%0,%1,%2,%3};\n"
        : "+f"(d[0]), "+f"(d[1]), "+f"(d[2]), "+f"(d[3])
        : "r"(__float_as_uint(a.x)), "r"(__float_as_uint(a.y)),
          "r"(__float_as_uint(a.z)), "r"(__float_as_uint(a.w)),
          "r"(__float_as_uint(b.x)), "r"(__float_as_uint(b.y)));
}
__device__ __forceinline__ void mma_bf16(float (&d)[4], const uint4 &a, const uint2 &b) {
    asm volatile(
        "mma.sync.aligned.m16n8k16.row.col.f32.bf16.bf16.f32 "
        "{%0,%1,%2,%3}, {%4,%5,%6,%7}, {%8,%9}, {%0,%1,%2,%3};\n"
        : "+f"(d[0]), "+f"(d[1]), "+f"(d[2]), "+f"(d[3])
        : "r"(a.x), "r"(a.y), "r"(a.z), "r"(a.w), "r"(b.x), "r"(b.y));
}
__device__ __forceinline__ uint32_t pbf2(float lo, float hi) {
    return (uint32_t)__bfloat16_as_ushort(__float2bfloat16_rn(lo))
         | ((uint32_t)__bfloat16_as_ushort(__float2bfloat16_rn(hi)) << 16);
}

// ---------------- weight transpose (both weights in one launch) ----------------
__global__ __launch_bounds__(256) void wtrans_kernel(const float* __restrict__ w1,
                                                     const float* __restrict__ w2) {
    int co = blockIdx.x;
    int cin = threadIdx.x;
    const float* w   = blockIdx.y ? w2 : w1;
    float*       wt  = blockIdx.y ? g_wt2 : g_wt;
    const float* src = w + (size_t)co * KCONV + (size_t)cin * 27;
    float v[27];
    #pragma unroll
    for (int t = 0; t < 27; t++) v[t] = src[t];
    float* dst = wt + (size_t)co * KCONV + cin;
    #pragma unroll
    for (int t = 0; t < 27; t++) dst[t * 256] = v[t];
}

// ---------------- pad kernel: x -> g_pad (zero-fill then direct interior map) ----------------
__global__ void pad_kernel(const float* __restrict__ x) {
    int bc = blockIdx.x;
    const float* src = x + (size_t)bc * NP;
    float* dst = g_pad + (size_t)bc * PADN;
    int tid = threadIdx.x;
    float4 z4 = make_float4(0.f, 0.f, 0.f, 0.f);
    #pragma unroll
    for (int s = 0; s < 6; s++) {
        int i = tid + s * 256;
        if (i < PADN / 4) *(float4*)(dst + i * 4) = z4;
    }
    __syncthreads();
    #pragma unroll
    for (int s = 0; s < 16; s++) {
        int idx = tid + s * 256;
        int zc = idx & 15, yc = (idx >> 4) & 15, xc = idx >> 8;
        dst[(xc + 1) * 324 + (yc + 1) * 18 + (zc + 1)] = src[idx];
    }
}

// ---------------- block-wide mean/rstd of src (float4-vectorized reduction) ----------------
__device__ __forceinline__ void block_stats(const float* __restrict__ src,
                                            float& mean, float& rstd) {
    float s = 0.f, ss = 0.f;
    const float4* s4 = (const float4*)src;
    #pragma unroll
    for (int i = threadIdx.x; i < NP / 4; i += 256) {
        float4 v = s4[i];
        s  += v.x + v.y + v.z + v.w;
        ss += v.x * v.x + v.y * v.y + v.z * v.z + v.w * v.w;
    }
    #pragma unroll
    for (int o = 16; o; o >>= 1) {
        s  += __shfl_down_sync(0xffffffffu, s, o);
        ss += __shfl_down_sync(0xffffffffu, ss, o);
    }
    __shared__ float sh_s[8], sh_ss[8], sh_m, sh_r;
    int w = threadIdx.x >> 5, l = threadIdx.x & 31;
    if (l == 0) { sh_s[w] = s; sh_ss[w] = ss; }
    __syncthreads();
    if (threadIdx.x == 0) {
        float S = 0.f, SS = 0.f;
        #pragma unroll
        for (int i = 0; i < 8; i++) { S += sh_s[i]; SS += sh_ss[i]; }
        float m = S * (1.0f / NP);
        float var = SS * (1.0f / NP) - m * m;
        sh_m = m;
        sh_r = rsqrtf(var + EPSV);
    }
    __syncthreads();
    mean = sh_m; rstd = sh_r;
}

// ---------------- fused: stats(g_y[bc]) then instnorm+relu -> g_pad (zero+interior) ----------------
__global__ void stats_pad_kernel() {
    int bc = blockIdx.x;
    const float* src = g_y + (size_t)bc * NP;
    float m, r;
    block_stats(src, m, r);
    float* dst = g_pad + (size_t)bc * PADN;
    int tid = threadIdx.x;
    float4 z4 = make_float4(0.f, 0.f, 0.f, 0.f);
    #pragma unroll
    for (int s = 0; s < 6; s++) {
        int i = tid + s * 256;
        if (i < PADN / 4) *(float4*)(dst + i * 4) = z4;
    }
    __syncthreads();
    #pragma unroll
    for (int s = 0; s < 16; s++) {
        int idx = tid + s * 256;
        int zc = idx & 15, yc = (idx >> 4) & 15, xc = idx >> 8;
        dst[(xc + 1) * 324 + (yc + 1) * 18 + (zc + 1)] = fmaxf((src[idx] - m) * r, 0.f);
    }
}

// ---------------- fused: stats(g_y[bc]) then g_out = x + instnorm(g_y), float4 ----------------
__global__ void stats_norm_kernel(const float* __restrict__ x) {
    int bc = blockIdx.x;
    const float* src = g_y + (size_t)bc * NP;
    float m, r;
    block_stats(src, m, r);
    const float4* x4 = (const float4*)(x + (size_t)bc * NP);
    const float4* y4 = (const float4*)src;
    float4* d4 = (float4*)(g_out + (size_t)bc * NP);
    #pragma unroll
    for (int i = threadIdx.x; i < NP / 4; i += 256) {
        float4 a = x4[i], b = y4[i];
        d4[i] = make_float4(a.x + (b.x - m) * r, a.y + (b.y - m) * r,
                            a.z + (b.z - m) * r, a.w + (b.w - m) * r);
    }
}

// ============================================================================
// Pipelined mma.sync tf32 GEMM, 128x128 tile, k-step 32, 2-stage smem.
// MODE 0 (CONV):  A=wt[co][(tap,cin)], B=im2col(g_pad), dst=g_y fp32 (+bias)
// MODE 1 (VPROJ): A=Aext(wv),          B=g_out[c][p],   dst=g_vh bf16 (+bias)
// ============================================================================
#define STG_FLOATS 8320
#define SMEM_DYN (2 * STG_FLOATS * 4)

template<int MODE, int KTOT, int CONVSEL>
__global__ __launch_bounds__(256, 1)
void tc_gemm(const float* __restrict__ Aext, const float* __restrict__ bias) {
    constexpr int NCH = KTOT / 32;
    extern __shared__ float sm[];
    const int tid = threadIdx.x, wid = tid >> 5, lane = tid & 31;
    const int bb = blockIdx.z;
    const int m0 = blockIdx.y * 128, n0 = blockIdx.x * 128;

    // ---- A loader ----
    const int amt = tid >> 5;
    const int arg = (tid >> 2) & 7;
    const int akb = tid & 3;
    const float* aptr0;
    const float* aptr1;
    {
        int m = m0 + amt * 16 + arg;
        const float* base = (MODE == 0) ? (CONVSEL ? g_wt2 : g_wt) : Aext;
        aptr0 = base + (size_t)m * KTOT + akb * 8;
        aptr1 = base + (size_t)(m + 8) * KTOT + akb * 8;
    }

    // ---- B loader ----
    const int bn = tid >> 1;
    const int bkh = (tid & 1) * 2;
    int pofs = 0;
    const float* bbase = nullptr;
    if (MODE == 0) {
        int p = n0 + bn;
        int pz = p & 15, py = (p >> 4) & 15, px = p >> 8;
        pofs = (px + 1) * 324 + (py + 1) * 18 + (pz + 1);
        bbase = g_pad + (size_t)bb * CC * PADN;
    } else {
        bbase = g_out + (size_t)bb * CC * NP + n0 + bn;
    }

    float ar0[8], ar1[8], br[16];

    #define LOAD_A(ch_) do { \
        *(float4*)(ar0)     = *(const float4*)(aptr0 + (size_t)(ch_) * 32); \
        *(float4*)(ar0 + 4) = *(const float4*)(aptr0 + (size_t)(ch_) * 32 + 4); \
        *(float4*)(ar1)     = *(const float4*)(aptr1 + (size_t)(ch_) * 32); \
        *(float4*)(ar1 + 4) = *(const float4*)(aptr1 + (size_t)(ch_) * 32 + 4); \
    } while (0)

    #define LOAD_B(ch_) do { \
        if (MODE == 0) { \
            _Pragma("unroll") \
            for (int t = 0; t < 2; t++) { \
                _Pragma("unroll") \
                for (int c = 0; c < 8; c++) { \
                    int k = (ch_) * 32 + (bkh + t) * 8 + c; \
                    int tap = k >> 8, cin = k & 255; \
                    br[t * 8 + c] = bbase[(size_t)cin * PADN + c_doff[tap] + pofs]; \
                } \
            } \
        } else { \
            _Pragma("unroll") \
            for (int t = 0; t < 2; t++) { \
                _Pragma("unroll") \
                for (int c = 0; c < 8; c++) { \
                    int k = (ch_) * 32 + (bkh + t) * 8 + c; \
                    br[t * 8 + c] = bbase[(size_t)k * NP]; \
                } \
            } \
        } \
    } while (0)

    #define STORE_AB(stg_) do { \
        float* As_ = sm + (stg_) * STG_FLOATS + amt * 512 + akb * 128 + arg * 16; \
        _Pragma("unroll") \
        for (int c = 0; c < 4; c++) { \
            *(float4*)(As_ + c * 4) = make_float4( \
                tf32r(ar0[c]), tf32r(ar1[c]), tf32r(ar0[c + 4]), tf32r(ar1[c + 4])); \
        } \
        float* Bs_ = sm + (stg_) * STG_FLOATS + 4096 + (bn >> 3) * 264 + (bn & 7) * 8; \
        _Pragma("unroll") \
        for (int t = 0; t < 2; t++) { \
            int kbb = bkh + t; \
            _Pragma("unroll") \
            for (int c = 0; c < 4; c++) { \
                *(float2*)(Bs_ + kbb * 64 + c * 2) = \
                    make_float2(tf32r(br[t * 8 + c]), tf32r(br[t * 8 + c + 4])); \
            } \
        } \
    } while (0)

    const int wm = wid & 1, wn = wid >> 1;
    float acc[4][4][4];
    #pragma unroll
    for (int i = 0; i < 4; i++)
        #pragma unroll
        for (int j = 0; j < 4; j++)
            #pragma unroll
            for (int k = 0; k < 4; k++) acc[i][j][k] = 0.f;

    LOAD_A(0); LOAD_B(0);
    STORE_AB(0);
    LOAD_A(1); LOAD_B(1);
    __syncthreads();

    for (int ch = 0; ch < NCH; ch++) {
        int cur = ch & 1;
        if (ch + 1 < NCH) STORE_AB(cur ^ 1);
        if (ch + 2 < NCH) { LOAD_A(ch + 2); LOAD_B(ch + 2); }

        const float* As_ = sm + cur * STG_FLOATS;
        const float* Bs_ = As_ + 4096;
        #pragma unroll
        for (int kb = 0; kb < 4; kb++) {
            float4 af[4]; float2 bf[4];
            #pragma unroll
            for (int mt = 0; mt < 4; mt++)
                af[mt] = *(const float4*)(As_ + (wm * 4 + mt) * 512 + kb * 128 + lane * 4);
            #pragma unroll
            for (int nt = 0; nt < 4; nt++)
                bf[nt] = *(const float2*)(Bs_ + (wn * 4 + nt) * 264 + kb * 64 + lane * 2);
            #pragma unroll
            for (int mt = 0; mt < 4; mt++)
                #pragma unroll
                for (int nt = 0; nt < 4; nt++)
                    mma_tf32(acc[mt][nt], af[mt], bf[nt]);
        }
        __syncthreads();
    }

    #undef LOAD_A
    #undef LOAD_B
    #undef STORE_AB

    const int g = lane >> 2, tg = lane & 3;
    #pragma unroll
    for (int mt = 0; mt < 4; mt++) {
        int m = m0 + wm * 64 + mt * 16 + g;
        float bs0 = bias[m], bs1 = bias[m + 8];
        #pragma unroll
        for (int nt = 0; nt < 4; nt++) {
            int n = n0 + wn * 32 + nt * 8 + tg * 2;
            size_t base0 = (size_t)(bb * CC + m) * NP + n;
            size_t base1 = base0 + (size_t)8 * NP;
            if (MODE == 0) {
                *(float2*)(g_y + base0) = make_float2(acc[mt][nt][0] + bs0, acc[mt][nt][1] + bs0);
                *(float2*)(g_y + base1) = make_float2(acc[mt][nt][2] + bs1, acc[mt][nt][3] + bs1);
            } else {
                *(uint32_t*)(g_vh + base0) = pbf2(acc[mt][nt][0] + bs0, acc[mt][nt][1] + bs0);
                *(uint32_t*)(g_vh + base1) = pbf2(acc[mt][nt][2] + bs1, acc[mt][nt][3] + bs1);
            }
        }
    }
}

// ============================================================================
// o-GEMM, bf16 m16n8k16: o[c,i] = sum_j v[c,j]*attnh[i,j]; dout = gamma*o+g_out
// ============================================================================
#define OA_U32 2048
#define OB_U32 (16*136)
#define OSTG_U32 (OA_U32 + OB_U32)
#define OSMEM (2 * OSTG_U32 * 4)

__global__ __launch_bounds__(256, 1)
void o_gemm_bf16(const float* __restrict__ gamma, float* __restrict__ dout) {
    extern __shared__ uint32_t smu[];
    const int tid = threadIdx.x, wid = tid >> 5, lane = tid & 31;
    const int bb = blockIdx.z, m0 = blockIdx.y * 128, i0 = blockIdx.x * 128;
    const int wm = wid & 1, wn = wid >> 1;

    const uint32_t *av0 = nullptr, *av1 = nullptr;
    uint32_t aoff = 0;
    if (tid < 128) {
        int rpi = tid >> 1, akb = tid & 1;
        int mt = rpi >> 3, rp = rpi & 7;
        int m = m0 + mt * 16 + rp;
        av0 = (const uint32_t*)(g_vh + (size_t)(bb * CC + m) * NP) + akb * 8;
        av1 = av0 + (size_t)4 * NP;    // +8 rows of NP bf16 = 4*NP u32
        aoff = mt * 256 + akb * 128 + rp * 16;
    }
    const int bn = tid >> 1, bkb = tid & 1;
    const __nv_bfloat16* bptr = g_attnh + ((size_t)bb * NP + i0 + bn) * NP + bkb * 16;
    const uint32_t boff = OA_U32 + (bn >> 3) * 136 + bkb * 68 + (bn & 7) * 8;

    uint32_t a0u[8], a1u[8];
    uint32_t brg[8];

    #define OLOAD(ch_) do { \
        if (tid < 128) { \
            *(uint4*)(a0u)     = *(const uint4*)(av0 + (size_t)(ch_) * 16); \
            *(uint4*)(a0u + 4) = *(const uint4*)(av0 + (size_t)(ch_) * 16 + 4); \
            *(uint4*)(a1u)     = *(const uint4*)(av1 + (size_t)(ch_) * 16); \
            *(uint4*)(a1u + 4) = *(const uint4*)(av1 + (size_t)(ch_) * 16 + 4); \
        } \
        *(uint4*)(brg)     = *(const uint4*)(bptr + (size_t)(ch_) * 32); \
        *(uint4*)(brg + 4) = *(const uint4*)(bptr + (size_t)(ch_) * 32 + 8); \
    } while (0)

    #define OSTORE(stg_) do { \
        uint32_t* s_ = smu + (stg_) * OSTG_U32; \
        if (tid < 128) { \
            _Pragma("unroll") \
            for (int t = 0; t < 4; t++) { \
                *(uint4*)(s_ + aoff + t * 4) = \
                    make_uint4(a0u[t], a1u[t], a0u[t + 4], a1u[t + 4]); \
            } \
        } \
        _Pragma("unroll") \
        for (int t = 0; t < 4; t++) \
            *(uint2*)(s_ + boff + t * 2) = make_uint2(brg[t], brg[t + 4]); \
    } while (0)

    float acc[4][4][4];
    #pragma unroll
    for (int i = 0; i < 4; i++)
        #pragma unroll
        for (int j = 0; j < 4; j++)
            #pragma unroll
            for (int k = 0; k < 4; k++) acc[i][j][k] = 0.f;

    OLOAD(0); OSTORE(0); OLOAD(1);
    __syncthreads();

    constexpr int NCH = NP / 32;   // 128
    for (int ch = 0; ch < NCH; ch++) {
        int cur = ch & 1;
        if (ch + 1 < NCH) OSTORE(cur ^ 1);
        if (ch + 2 < NCH) OLOAD(ch + 2);

        const uint32_t* s_ = smu + cur * OSTG_U32;
        #pragma unroll
        for (int kb = 0; kb < 2; kb++) {
            uint4 af[4]; uint2 bf[4];
            #pragma unroll
            for (int mt = 0; mt < 4; mt++)
                af[mt] = *(const uint4*)(s_ + (wm * 4 + mt) * 256 + kb * 128 + lane * 4);
            #pragma unroll
            for (int nt = 0; nt < 4; nt++)
                bf[nt] = *(const uint2*)(s_ + OA_U32 + (wn * 4 + nt) * 136 + kb * 68 + lane * 2);
            #pragma unroll
            for (int mt = 0; mt < 4; mt++)
                #pragma unroll
                for (int nt = 0; nt < 4; nt++)
                    mma_bf16(acc[mt][nt], af[mt], bf[nt]);
        }
        __syncthreads();
    }

    #undef OLOAD
    #undef OSTORE

    const int g = lane >> 2, tg = lane & 3;
    const float gm = gamma[0];
    #pragma unroll
    for (int mt = 0; mt < 4; mt++) {
        int m = m0 + wm * 64 + mt * 16 + g;
        #pragma unroll
        for (int nt = 0; nt < 4; nt++) {
            int n = i0 + wn * 32 + nt * 8 + tg * 2;
            size_t base0 = (size_t)(bb * CC + m) * NP + n;
            size_t base1 = base0 + (size_t)8 * NP;
            const float* r0 = g_out + base0;
            const float* r1 = g_out + base1;
            *(float2*)(dout + base0) =
                make_float2(gm * acc[mt][nt][0] + r0[0], gm * acc[mt][nt][1] + r0[1]);
            *(float2*)(dout + base1) =
                make_float2(gm * acc[mt][nt][2] + r1[0], gm * acc[mt][nt][3] + r1[1]);
        }
    }
}

// ---------------- energy -> bf16 g_attnh ----------------
__global__ __launch_bounds__(256) void energy_tc() {
    __shared__ float As[8][2][32][4];
    __shared__ float Bs[16][2][32][2];
    int tid = threadIdx.x, b = blockIdx.z;
    int i0 = blockIdx.y * 128, j0 = blockIdx.x * 128;

    int cl = tid >> 4, ig = tid & 15;
    int ckblk = cl >> 3, ckc = cl & 7;

    int wid = tid >> 5, lane = tid & 31;
    int wm = wid & 1, wn = wid >> 1;

    float acc[4][4][4];
    #pragma unroll
    for (int i = 0; i < 4; i++)
        #pragma unroll
        for (int j = 0; j < 4; j++)
            #pragma unroll
            for (int k = 0; k < 4; k++) acc[i][j][k] = 0.f;

    #pragma unroll
    for (int it = 0; it < 2; ++it) {
        int c = it * 16 + cl;
        const float* qsrc = g_q + (size_t)(b * C8 + c) * NP + i0 + ig * 8;
        const float* ksrc = g_k + (size_t)(b * C8 + c) * NP + j0 + ig * 8;
        float4 q0 = *(const float4*)qsrc, q1 = *(const float4*)(qsrc + 4);
        float4 k0 = *(const float4*)ksrc, k1 = *(const float4*)(ksrc + 4);

        __syncthreads();
        {
            float qv[8] = {q0.x, q0.y, q0.z, q0.w, q1.x, q1.y, q1.z, q1.w};
            #pragma unroll
            for (int ii = 0; ii < 8; ii++) {
                int r = ig * 8 + ii;
                int mtile = r >> 4, rr = r & 15;
                As[mtile][ckblk][(rr & 7) * 4 + (ckc & 3)][(rr >> 3) + ((ckc >> 2) << 1)] = tf32r(qv[ii]);
            }
            float kv[8] = {k0.x, k0.y, k0.z, k0.w, k1.x, k1.y, k1.z, k1.w};
            #pragma unroll
            for (int nn = 0; nn < 8; nn++)
                Bs[ig][ckblk][nn * 4 + (ckc & 3)][ckc >> 2] = tf32r(kv[nn]);
        }
        __syncthreads();

        #pragma unroll
        for (int kb = 0; kb < 2; kb++) {
            float4 af[4]; float2 bf[4];
            #pragma unroll
            for (int mt = 0; mt < 4; mt++) af[mt] = *(const float4*)As[wm * 4 + mt][kb][lane];
            #pragma unroll
            for (int nt = 0; nt < 4; nt++) bf[nt] = *(const float2*)Bs[wn * 4 + nt][kb][lane];
            #pragma unroll
            for (int mt = 0; mt < 4; mt++)
                #pragma unroll
                for (int nt = 0; nt < 4; nt++)
                    mma_tf32(acc[mt][nt], af[mt], bf[nt]);
        }
    }

    int g = lane >> 2, tg = lane & 3;
    #pragma unroll
    for (int mt = 0; mt < 4; mt++) {
        int m = i0 + wm * 64 + mt * 16 + g;
        #pragma unroll
        for (int nt = 0; nt < 4; nt++) {
            int n = j0 + wn * 32 + nt * 8 + tg * 2;
            __nv_bfloat16* d0 = g_attnh + ((size_t)b * NP + m) * NP + n;
            *(uint32_t*)d0 = pbf2(acc[mt][nt][0], acc[mt][nt][1]);
            *(uint32_t*)(d0 + (size_t)8 * NP) = pbf2(acc[mt][nt][2], acc[mt][nt][3]);
        }
    }
}

// ---------------- q and k projections fused (FFMA, small) ----------------
__global__ __launch_bounds__(256) void qk_gemm(const float* __restrict__ wq, const float* __restrict__ bq,
                                               const float* __restrict__ wk, const float* __restrict__ bk) {
    __shared__ float As[8][64];
    __shared__ float Bs[8][128];
    int tid = threadIdx.x, b = blockIdx.z;
    int p0 = blockIdx.x * 128;
    int arow = tid >> 2;
    int acol = (tid & 3) * 2;
    const float* ap = ((arow < 32) ? (wq + arow * CC) : (wk + (arow - 32) * CC)) + acol;
    int brow = tid >> 5, bcol = (tid & 31) * 4;
    const float* bp = g_out + (b * CC + brow) * NP + p0 + bcol;
    int ty = tid >> 4, tx = tid & 15;
    float acc[4][8];
    #pragma unroll
    for (int i = 0; i < 4; i++)
        #pragma unroll
        for (int j = 0; j < 8; j++) acc[i][j] = 0.f;

    for (int it = 0; it < CC / 8; ++it) {
        float2 av = *(const float2*)(ap + it * 8);
        float4 bv = *(const float4*)(bp + (size_t)it * 8 * NP);
        __syncthreads();
        As[acol + 0][arow] = av.x;
        As[acol + 1][arow] = av.y;
        *(float4*)&Bs[brow][bcol] = bv;
        __syncthreads();
        #pragma unroll
        for (int kk = 0; kk < 8; kk++) {
            float a[4], bvv[8];
            float4 t0 = *(const float4*)&As[kk][ty * 4];
            a[0]=t0.x; a[1]=t0.y; a[2]=t0.z; a[3]=t0.w;
            float4 u0 = *(const float4*)&Bs[kk][tx * 8];
            float4 u1 = *(const float4*)&Bs[kk][tx * 8 + 4];
            bvv[0]=u0.x; bvv[1]=u0.y; bvv[2]=u0.z; bvv[3]=u0.w;
            bvv[4]=u1.x; bvv[5]=u1.y; bvv[6]=u1.z; bvv[7]=u1.w;
            #pragma unroll
            for (int i = 0; i < 4; i++)
                #pragma unroll
                for (int j = 0; j < 8; j++)
                    acc[i][j] += a[i] * bvv[j];
        }
    }
    #pragma unroll
    for (int i = 0; i < 4; i++) {
        int row = ty * 4 + i;
        float bias = (row < 32) ? bq[row] : bk[row - 32];
        float* dst = ((row < 32) ? (g_q + (b * C8 + row) * NP)
                                 : (g_k + (b * C8 + row - 32) * NP)) + p0 + tx * 8;
        *(float4*)dst       = make_float4(acc[i][0]+bias, acc[i][1]+bias, acc[i][2]+bias, acc[i][3]+bias);
        *(float4*)(dst + 4) = make_float4(acc[i][4]+bias, acc[i][5]+bias, acc[i][6]+bias, acc[i][7]+bias);
    }
}

// ---------------- row softmax over 4096, bf16 in place (u32-vectorized) ----------------
__global__ __launch_bounds__(256) void softmax_kernel() {
    size_t row = blockIdx.x;
    uint32_t* ptr = (uint32_t*)(g_attnh + row * (size_t)NP);   // 2048 u32
    int tid = threadIdx.x;
    float vals[16];
    float m = -1e30f;
    #pragma unroll
    for (int s = 0; s < 8; s++) {
        uint32_t u = ptr[tid + s * 256];
        float lo = __bfloat162float(__ushort_as_bfloat16((unsigned short)(u & 0xffff)));
        float hi = __bfloat162float(__ushort_as_bfloat16((unsigned short)(u >> 16)));
        vals[2 * s] = lo; vals[2 * s + 1] = hi;
        m = fmaxf(m, fmaxf(lo, hi));
    }
    #pragma unroll
    for (int o = 16; o; o >>= 1) m = fmaxf(m, __shfl_xor_sync(0xffffffffu, m, o));
    __shared__ float shm[8], shs[8];
    int w = tid >> 5, l = tid & 31;
    if (l == 0) shm[w] = m;
    __syncthreads();
    m = fmaxf(fmaxf(fmaxf(shm[0], shm[1]), fmaxf(shm[2], shm[3])),
              fmaxf(fmaxf(shm[4], shm[5]), fmaxf(shm[6], shm[7])));
    float sum = 0.f;
    #pragma unroll
    for (int s = 0; s < 16; s++) {
        vals[s] = __expf(vals[s] - m);
        sum += vals[s];
    }
    #pragma unroll
    for (int o = 16; o; o >>= 1) sum += __shfl_xor_sync(0xffffffffu, sum, o);
    if (l == 0) shs[w] = sum;
    __syncthreads();
    sum = shs[0] + shs[1] + shs[2] + shs[3] + shs[4] + shs[5] + shs[6] + shs[7];
    float inv = 1.0f / sum;
    #pragma unroll
    for (int s = 0; s < 8; s++)
        ptr[tid + s * 256] = pbf2(vals[2 * s] * inv, vals[2 * s + 1] * inv);
}

// ---------------- launcher: forked-stream capture graph ----------------
extern "C" void kernel_launch(void* const* d_in, const int* in_sizes, int n_in,
                              void* d_out, int out_size) {
    const float* x     = (const float*)d_in[0];
    const float* w1    = (const float*)d_in[1];
    const float* b1    = (const float*)d_in[2];
    const float* w2    = (const float*)d_in[3];
    const float* b2    = (const float*)d_in[4];
    const float* wq    = (const float*)d_in[5];
    const float* bq    = (const float*)d_in[6];
    const float* wk    = (const float*)d_in[7];
    const float* bk    = (const float*)d_in[8];
    const float* wv    = (const float*)d_in[9];
    const float* bv    = (const float*)d_in[10];
    const float* gamma = (const float*)d_in[11];
    float* out = (float*)d_out;

    cudaFuncSetAttribute(tc_gemm<0, KCONV, 0>, cudaFuncAttributeMaxDynamicSharedMemorySize, SMEM_DYN);
    cudaFuncSetAttribute(tc_gemm<0, KCONV, 1>, cudaFuncAttributeMaxDynamicSharedMemorySize, SMEM_DYN);
    cudaFuncSetAttribute(tc_gemm<1, CC, 0>,    cudaFuncAttributeMaxDynamicSharedMemorySize, SMEM_DYN);
    cudaFuncSetAttribute(o_gemm_bf16,          cudaFuncAttributeMaxDynamicSharedMemorySize, OSMEM);

    // Side stream for independent work. NOTE: created fresh each call and NOT
    // destroyed — destroying a stream participating in an active capture would
    // invalidate the capture. Leaks a few handles over the run; harmless.
    cudaStream_t s1;
    cudaStreamCreateWithFlags(&s1, cudaStreamNonBlocking);
    cudaEvent_t evA, evB, evC, evD;
    cudaEventCreateWithFlags(&evA, cudaEventDisableTiming);
    cudaEventCreateWithFlags(&evB, cudaEventDisableTiming);
    cudaEventCreateWithFlags(&evC, cudaEventDisableTiming);
    cudaEventCreateWithFlags(&evD, cudaEventDisableTiming);

    dim3 g128(NP / 128, CC / 128, BB);   // (32,2,2)

    // fork: wtrans on s1 overlaps pad on main stream
    cudaEventRecord(evA, 0);
    cudaStreamWaitEvent(s1, evA, 0);
    wtrans_kernel<<<dim3(CC, 2), 256, 0, s1>>>(w1, w2);
    pad_kernel<<<BB * CC, 256>>>(x);
    cudaEventRecord(evB, s1);
    cudaStreamWaitEvent(0, evB, 0);

    // conv chain (serial by data dependence)
    tc_gemm<0, KCONV, 0><<<g128, 256, SMEM_DYN>>>(nullptr, b1);
    stats_pad_kernel<<<BB * CC, 256>>>();
    tc_gemm<0, KCONV, 1><<<g128, 256, SMEM_DYN>>>(nullptr, b2);
    stats_norm_kernel<<<BB * CC, 256>>>(x);

    // fork: v-projection (s1) overlaps qk -> energy -> softmax (main)
    cudaEventRecord(evC, 0);
    cudaStreamWaitEvent(s1, evC, 0);
    tc_gemm<1, CC, 0><<<g128, 256, SMEM_DYN, s1>>>(wv, bv);
    qk_gemm<<<dim3(NP / 128, 1, BB), 256>>>(wq, bq, wk, bk);
    energy_tc<<<dim3(NP / 128, NP / 128, BB), 256>>>();
    softmax_kernel<<<BB * NP, 256>>>();
    cudaEventRecord(evD, s1);
    cudaStreamWaitEvent(0, evD, 0);

    // join: o-GEMM needs both g_vh (s1) and g_attnh (main)
    o_gemm_bf16<<<g128, 256, OSMEM>>>(gamma, out);
}

// round 13
// speedup vs baseline: 1.3265x; 1.0143x over previous
#include <cuda_runtime.h>
#include <cuda_bf16.h>
#include <math.h>
#include <stdint.h>

#define EPSV 1e-5f
#define BB 2
#define CC 256
#define C8 32
#define NP 4096          // 16*16*16 positions
#define PADN 5832        // 18*18*18
#define KCONV (CC*27)    // 6912

// ---------------- scratch ----------------
__device__ float g_pad[BB*CC*PADN];
__device__ float g_y[BB*CC*NP];
__device__ float g_out[BB*CC*NP];
__device__ float g_q[BB*C8*NP];
__device__ float g_k[BB*C8*NP];
__device__ __nv_bfloat16 g_vh[BB*CC*NP];             // bf16 V (only consumer is bf16 o-GEMM)
__device__ __nv_bfloat16 g_attnh[(size_t)BB*NP*NP];  // bf16 energies -> softmaxed in place
__device__ float g_wt[CC*KCONV];     // transposed conv1 weights: wt[co][tap*256+cin]
__device__ float g_wt2[CC*KCONV];    // transposed conv2 weights

// padded-offset per conv tap (strides 324/18/1)
__constant__ int c_doff[27] = {
  -343,-342,-341,-325,-324,-323,-307,-306,-305,
   -19, -18, -17,  -1,   0,   1,  17,  18,  19,
   305, 306, 307, 323, 324, 325, 341, 342, 343};

// ---------------- helpers ----------------
__device__ __forceinline__ float tf32r(float x) {
    uint32_t u;
    asm("cvt.rna.tf32.f32 %0, %1;" : "=r"(u) : "f"(x));
    return __uint_as_float(u);
}
__device__ __forceinline__ void mma_tf32(float (&d)[4], const float4 &a, const float2 &b) {
    asm volatile(
        "mma.sync.aligned.m16n8k8.row.col.f32.tf32.tf32.f32 "
        "{%0,%1,%2,%3}, {%4,%5,%6,%7}, {%8,%9}, {%0,%1,%2,%3};\n"
        : "+f"(d[0]), "+f"(d[1]), "+f"(d[2]), "+f"(d[3])
        : "r"(__float_as_uint(a.x)), "r"(__float_as_uint(a.y)),
          "r"(__float_as_uint(a.z)), "r"(__float_as_uint(a.w)),
          "r"(__float_as_uint(b.x)), "r"(__float_as_uint(b.y)));
}
__device__ __forceinline__ void mma_bf16(float (&d)[4], const uint4 &a, const uint2 &b) {
    asm volatile(
        "mma.sync.aligned.m16n8k16.row.col.f32.bf16.bf16.f32 "
        "{%0,%1,%2,%3}, {%4,%5,%6,%7}, {%8,%9}, {%0,%1,%2,%3};\n"
        : "+f"(d[0]), "+f"(d[1]), "+f"(d[2]), "+f"(d[3])
        : "r"(a.x), "r"(a.y), "r"(a.z), "r"(a.w), "r"(b.x), "r"(b.y));
}
__device__ __forceinline__ uint32_t pbf2(float lo, float hi) {
    return (uint32_t)__bfloat16_as_ushort(__float2bfloat16_rn(lo))
         | ((uint32_t)__bfloat16_as_ushort(__float2bfloat16_rn(hi)) << 16);
}

// ---------------- weight transpose (both weights in one launch) ----------------
__global__ __launch_bounds__(256) void wtrans_kernel(const float* __restrict__ w1,
                                                     const float* __restrict__ w2) {
    int co = blockIdx.x;
    int cin = threadIdx.x;
    const float* w   = blockIdx.y ? w2 : w1;
    float*       wt  = blockIdx.y ? g_wt2 : g_wt;
    const float* src = w + (size_t)co * KCONV + (size_t)cin * 27;
    float v[27];
    #pragma unroll
    for (int t = 0; t < 27; t++) v[t] = src[t];
    float* dst = wt + (size_t)co * KCONV + cin;
    #pragma unroll
    for (int t = 0; t < 27; t++) dst[t * 256] = v[t];
}

// ---------------- pad kernel: x -> g_pad (zero-fill then direct interior map) ----------------
__global__ void pad_kernel(const float* __restrict__ x) {
    int bc = blockIdx.x;
    const float* src = x + (size_t)bc * NP;
    float* dst = g_pad + (size_t)bc * PADN;
    int tid = threadIdx.x;
    float4 z4 = make_float4(0.f, 0.f, 0.f, 0.f);
    #pragma unroll
    for (int s = 0; s < 6; s++) {
        int i = tid + s * 256;
        if (i < PADN / 4) *(float4*)(dst + i * 4) = z4;
    }
    __syncthreads();
    #pragma unroll
    for (int s = 0; s < 16; s++) {
        int idx = tid + s * 256;
        int zc = idx & 15, yc = (idx >> 4) & 15, xc = idx >> 8;
        dst[(xc + 1) * 324 + (yc + 1) * 18 + (zc + 1)] = src[idx];
    }
}

// ---------------- block-wide mean/rstd (float4-vectorized reduction) ----------------
__device__ __forceinline__ void block_stats(const float* __restrict__ src,
                                            float& mean, float& rstd) {
    float s = 0.f, ss = 0.f;
    const float4* s4 = (const float4*)src;
    #pragma unroll
    for (int i = threadIdx.x; i < NP / 4; i += 256) {
        float4 v = s4[i];
        s  += v.x + v.y + v.z + v.w;
        ss += v.x * v.x + v.y * v.y + v.z * v.z + v.w * v.w;
    }
    #pragma unroll
    for (int o = 16; o; o >>= 1) {
        s  += __shfl_down_sync(0xffffffffu, s, o);
        ss += __shfl_down_sync(0xffffffffu, ss, o);
    }
    __shared__ float sh_s[8], sh_ss[8], sh_m, sh_r;
    int w = threadIdx.x >> 5, l = threadIdx.x & 31;
    if (l == 0) { sh_s[w] = s; sh_ss[w] = ss; }
    __syncthreads();
    if (threadIdx.x == 0) {
        float S = 0.f, SS = 0.f;
        #pragma unroll
        for (int i = 0; i < 8; i++) { S += sh_s[i]; SS += sh_ss[i]; }
        float m = S * (1.0f / NP);
        float var = SS * (1.0f / NP) - m * m;
        sh_m = m;
        sh_r = rsqrtf(var + EPSV);
    }
    __syncthreads();
    mean = sh_m; rstd = sh_r;
}

// ---------------- fused: stats(g_y[bc]) then instnorm+relu -> g_pad ----------------
__global__ void stats_pad_kernel() {
    int bc = blockIdx.x;
    const float* src = g_y + (size_t)bc * NP;
    float m, r;
    block_stats(src, m, r);
    float* dst = g_pad + (size_t)bc * PADN;
    int tid = threadIdx.x;
    float4 z4 = make_float4(0.f, 0.f, 0.f, 0.f);
    #pragma unroll
    for (int s = 0; s < 6; s++) {
        int i = tid + s * 256;
        if (i < PADN / 4) *(float4*)(dst + i * 4) = z4;
    }
    __syncthreads();
    #pragma unroll
    for (int s = 0; s < 16; s++) {
        int idx = tid + s * 256;
        int zc = idx & 15, yc = (idx >> 4) & 15, xc = idx >> 8;
        dst[(xc + 1) * 324 + (yc + 1) * 18 + (zc + 1)] = fmaxf((src[idx] - m) * r, 0.f);
    }
}

// ---------------- fused: stats(g_y[bc]) then g_out = x + instnorm(g_y), float4 ----------------
__global__ void stats_norm_kernel(const float* __restrict__ x) {
    int bc = blockIdx.x;
    const float* src = g_y + (size_t)bc * NP;
    float m, r;
    block_stats(src, m, r);
    const float4* x4 = (const float4*)(x + (size_t)bc * NP);
    const float4* y4 = (const float4*)src;
    float4* d4 = (float4*)(g_out + (size_t)bc * NP);
    #pragma unroll
    for (int i = threadIdx.x; i < NP / 4; i += 256) {
        float4 a = x4[i], b = y4[i];
        d4[i] = make_float4(a.x + (b.x - m) * r, a.y + (b.y - m) * r,
                            a.z + (b.z - m) * r, a.w + (b.w - m) * r);
    }
}

// ============================================================================
// Pipelined mma.sync tf32 GEMM, 128x128 tile, k-step 32, 2-stage smem.
// MODE 0 (CONV):   A=wt[co][(tap,cin)],  B=im2col(g_pad), dst=g_y fp32 (+bias)
// MODE 1 (VPROJ):  A=Aext(wv),           B=g_out[c][p],   dst=g_vh bf16 (+bias)
// MODE 2 (ENERGY): A=q^T [i][c] strided, B=k [j][c] strided, KTOT=32,
//                  dst=g_attnh bf16 (no bias)
// ============================================================================
#define STG_FLOATS 8320
#define SMEM_DYN (2 * STG_FLOATS * 4)

template<int MODE, int KTOT, int CONVSEL>
__global__ __launch_bounds__(256, 1)
void tc_gemm(const float* __restrict__ Aext, const float* __restrict__ bias) {
    constexpr int NCH = KTOT / 32;
    extern __shared__ float sm[];
    const int tid = threadIdx.x, wid = tid >> 5, lane = tid & 31;
    const int bb = blockIdx.z;
    const int m0 = blockIdx.y * 128, n0 = blockIdx.x * 128;

    // ---- A loader ----
    const int amt = tid >> 5;
    const int arg = (tid >> 2) & 7;
    const int akb = tid & 3;
    const float* aptr0 = nullptr;
    const float* aptr1 = nullptr;
    const float* aqbase = nullptr;
    {
        int m = m0 + amt * 16 + arg;
        if (MODE == 2) {
            aqbase = g_q + (size_t)bb * C8 * NP + m;   // element k: aqbase[k*NP], row m+8: +8
        } else {
            const float* base = (MODE == 0) ? (CONVSEL ? g_wt2 : g_wt) : Aext;
            aptr0 = base + (size_t)m * KTOT + akb * 8;
            aptr1 = base + (size_t)(m + 8) * KTOT + akb * 8;
        }
    }

    // ---- B loader ----
    const int bn = tid >> 1;
    const int bkh = (tid & 1) * 2;
    int pofs = 0;
    const float* bbase = nullptr;
    if (MODE == 0) {
        int p = n0 + bn;
        int pz = p & 15, py = (p >> 4) & 15, px = p >> 8;
        pofs = (px + 1) * 324 + (py + 1) * 18 + (pz + 1);
        bbase = g_pad + (size_t)bb * CC * PADN;
    } else if (MODE == 1) {
        bbase = g_out + (size_t)bb * CC * NP + n0 + bn;
    } else {
        bbase = g_k + (size_t)bb * C8 * NP + n0 + bn;
    }

    float ar0[8], ar1[8], br[16];

    #define LOAD_A(ch_) do { \
        if (MODE == 2) { \
            _Pragma("unroll") \
            for (int c = 0; c < 8; c++) { \
                size_t o_ = (size_t)((ch_) * 32 + akb * 8 + c) * NP; \
                ar0[c] = aqbase[o_]; \
                ar1[c] = aqbase[o_ + 8]; \
            } \
        } else { \
            *(float4*)(ar0)     = *(const float4*)(aptr0 + (size_t)(ch_) * 32); \
            *(float4*)(ar0 + 4) = *(const float4*)(aptr0 + (size_t)(ch_) * 32 + 4); \
            *(float4*)(ar1)     = *(const float4*)(aptr1 + (size_t)(ch_) * 32); \
            *(float4*)(ar1 + 4) = *(const float4*)(aptr1 + (size_t)(ch_) * 32 + 4); \
        } \
    } while (0)

    #define LOAD_B(ch_) do { \
        if (MODE == 0) { \
            _Pragma("unroll") \
            for (int t = 0; t < 2; t++) { \
                _Pragma("unroll") \
                for (int c = 0; c < 8; c++) { \
                    int k = (ch_) * 32 + (bkh + t) * 8 + c; \
                    int tap = k >> 8, cin = k & 255; \
                    br[t * 8 + c] = bbase[(size_t)cin * PADN + c_doff[tap] + pofs]; \
                } \
            } \
        } else { \
            _Pragma("unroll") \
            for (int t = 0; t < 2; t++) { \
                _Pragma("unroll") \
                for (int c = 0; c < 8; c++) { \
                    int k = (ch_) * 32 + (bkh + t) * 8 + c; \
                    br[t * 8 + c] = bbase[(size_t)k * NP]; \
                } \
            } \
        } \
    } while (0)

    #define STORE_AB(stg_) do { \
        float* As_ = sm + (stg_) * STG_FLOATS + amt * 512 + akb * 128 + arg * 16; \
        _Pragma("unroll") \
        for (int c = 0; c < 4; c++) { \
            *(float4*)(As_ + c * 4) = make_float4( \
                tf32r(ar0[c]), tf32r(ar1[c]), tf32r(ar0[c + 4]), tf32r(ar1[c + 4])); \
        } \
        float* Bs_ = sm + (stg_) * STG_FLOATS + 4096 + (bn >> 3) * 264 + (bn & 7) * 8; \
        _Pragma("unroll") \
        for (int t = 0; t < 2; t++) { \
            int kbb = bkh + t; \
            _Pragma("unroll") \
            for (int c = 0; c < 4; c++) { \
                *(float2*)(Bs_ + kbb * 64 + c * 2) = \
                    make_float2(tf32r(br[t * 8 + c]), tf32r(br[t * 8 + c + 4])); \
            } \
        } \
    } while (0)

    const int wm = wid & 1, wn = wid >> 1;
    float acc[4][4][4];
    #pragma unroll
    for (int i = 0; i < 4; i++)
        #pragma unroll
        for (int j = 0; j < 4; j++)
            #pragma unroll
            for (int k = 0; k < 4; k++) acc[i][j][k] = 0.f;

    LOAD_A(0); LOAD_B(0);
    STORE_AB(0);
    if (NCH > 1) { LOAD_A(1); LOAD_B(1); }
    __syncthreads();

    for (int ch = 0; ch < NCH; ch++) {
        int cur = ch & 1;
        if (ch + 1 < NCH) STORE_AB(cur ^ 1);
        if (ch + 2 < NCH) { LOAD_A(ch + 2); LOAD_B(ch + 2); }

        const float* As_ = sm + cur * STG_FLOATS;
        const float* Bs_ = As_ + 4096;
        #pragma unroll
        for (int kb = 0; kb < 4; kb++) {
            float4 af[4]; float2 bf[4];
            #pragma unroll
            for (int mt = 0; mt < 4; mt++)
                af[mt] = *(const float4*)(As_ + (wm * 4 + mt) * 512 + kb * 128 + lane * 4);
            #pragma unroll
            for (int nt = 0; nt < 4; nt++)
                bf[nt] = *(const float2*)(Bs_ + (wn * 4 + nt) * 264 + kb * 64 + lane * 2);
            #pragma unroll
            for (int mt = 0; mt < 4; mt++)
                #pragma unroll
                for (int nt = 0; nt < 4; nt++)
                    mma_tf32(acc[mt][nt], af[mt], bf[nt]);
        }
        __syncthreads();
    }

    #undef LOAD_A
    #undef LOAD_B
    #undef STORE_AB

    const int g = lane >> 2, tg = lane & 3;
    #pragma unroll
    for (int mt = 0; mt < 4; mt++) {
        int m = m0 + wm * 64 + mt * 16 + g;
        float bs0 = 0.f, bs1 = 0.f;
        if (MODE != 2) { bs0 = bias[m]; bs1 = bias[m + 8]; }
        #pragma unroll
        for (int nt = 0; nt < 4; nt++) {
            int n = n0 + wn * 32 + nt * 8 + tg * 2;
            if (MODE == 0) {
                size_t base0 = (size_t)(bb * CC + m) * NP + n;
                size_t base1 = base0 + (size_t)8 * NP;
                *(float2*)(g_y + base0) = make_float2(acc[mt][nt][0] + bs0, acc[mt][nt][1] + bs0);
                *(float2*)(g_y + base1) = make_float2(acc[mt][nt][2] + bs1, acc[mt][nt][3] + bs1);
            } else if (MODE == 1) {
                size_t base0 = (size_t)(bb * CC + m) * NP + n;
                size_t base1 = base0 + (size_t)8 * NP;
                *(uint32_t*)(g_vh + base0) = pbf2(acc[mt][nt][0] + bs0, acc[mt][nt][1] + bs0);
                *(uint32_t*)(g_vh + base1) = pbf2(acc[mt][nt][2] + bs1, acc[mt][nt][3] + bs1);
            } else {
                size_t base0 = ((size_t)bb * NP + m) * NP + n;
                size_t base1 = base0 + (size_t)8 * NP;
                *(uint32_t*)(g_attnh + base0) = pbf2(acc[mt][nt][0], acc[mt][nt][1]);
                *(uint32_t*)(g_attnh + base1) = pbf2(acc[mt][nt][2], acc[mt][nt][3]);
            }
        }
    }
}

// ============================================================================
// o-GEMM, bf16 m16n8k16: o[c,i] = sum_j v[c,j]*attnh[i,j]; dout = gamma*o+g_out
// ============================================================================
#define OA_U32 2048
#define OB_U32 (16*136)
#define OSTG_U32 (OA_U32 + OB_U32)
#define OSMEM (2 * OSTG_U32 * 4)

__global__ __launch_bounds__(256, 1)
void o_gemm_bf16(const float* __restrict__ gamma, float* __restrict__ dout) {
    extern __shared__ uint32_t smu[];
    const int tid = threadIdx.x, wid = tid >> 5, lane = tid & 31;
    const int bb = blockIdx.z, m0 = blockIdx.y * 128, i0 = blockIdx.x * 128;
    const int wm = wid & 1, wn = wid >> 1;

    const uint32_t *av0 = nullptr, *av1 = nullptr;
    uint32_t aoff = 0;
    if (tid < 128) {
        int rpi = tid >> 1, akb = tid & 1;
        int mt = rpi >> 3, rp = rpi & 7;
        int m = m0 + mt * 16 + rp;
        av0 = (const uint32_t*)(g_vh + (size_t)(bb * CC + m) * NP) + akb * 8;
        av1 = av0 + (size_t)4 * NP;
        aoff = mt * 256 + akb * 128 + rp * 16;
    }
    const int bn = tid >> 1, bkb = tid & 1;
    const __nv_bfloat16* bptr = g_attnh + ((size_t)bb * NP + i0 + bn) * NP + bkb * 16;
    const uint32_t boff = OA_U32 + (bn >> 3) * 136 + bkb * 68 + (bn & 7) * 8;

    uint32_t a0u[8], a1u[8];
    uint32_t brg[8];

    #define OLOAD(ch_) do { \
        if (tid < 128) { \
            *(uint4*)(a0u)     = *(const uint4*)(av0 + (size_t)(ch_) * 16); \
            *(uint4*)(a0u + 4) = *(const uint4*)(av0 + (size_t)(ch_) * 16 + 4); \
            *(uint4*)(a1u)     = *(const uint4*)(av1 + (size_t)(ch_) * 16); \
            *(uint4*)(a1u + 4) = *(const uint4*)(av1 + (size_t)(ch_) * 16 + 4); \
        } \
        *(uint4*)(brg)     = *(const uint4*)(bptr + (size_t)(ch_) * 32); \
        *(uint4*)(brg + 4) = *(const uint4*)(bptr + (size_t)(ch_) * 32 + 8); \
    } while (0)

    #define OSTORE(stg_) do { \
        uint32_t* s_ = smu + (stg_) * OSTG_U32; \
        if (tid < 128) { \
            _Pragma("unroll") \
            for (int t = 0; t < 4; t++) { \
                *(uint4*)(s_ + aoff + t * 4) = \
                    make_uint4(a0u[t], a1u[t], a0u[t + 4], a1u[t + 4]); \
            } \
        } \
        _Pragma("unroll") \
        for (int t = 0; t < 4; t++) \
            *(uint2*)(s_ + boff + t * 2) = make_uint2(brg[t], brg[t + 4]); \
    } while (0)

    float acc[4][4][4];
    #pragma unroll
    for (int i = 0; i < 4; i++)
        #pragma unroll
        for (int j = 0; j < 4; j++)
            #pragma unroll
            for (int k = 0; k < 4; k++) acc[i][j][k] = 0.f;

    OLOAD(0); OSTORE(0); OLOAD(1);
    __syncthreads();

    constexpr int NCH = NP / 32;   // 128
    for (int ch = 0; ch < NCH; ch++) {
        int cur = ch & 1;
        if (ch + 1 < NCH) OSTORE(cur ^ 1);
        if (ch + 2 < NCH) OLOAD(ch + 2);

        const uint32_t* s_ = smu + cur * OSTG_U32;
        #pragma unroll
        for (int kb = 0; kb < 2; kb++) {
            uint4 af[4]; uint2 bf[4];
            #pragma unroll
            for (int mt = 0; mt < 4; mt++)
                af[mt] = *(const uint4*)(s_ + (wm * 4 + mt) * 256 + kb * 128 + lane * 4);
            #pragma unroll
            for (int nt = 0; nt < 4; nt++)
                bf[nt] = *(const uint2*)(s_ + OA_U32 + (wn * 4 + nt) * 136 + kb * 68 + lane * 2);
            #pragma unroll
            for (int mt = 0; mt < 4; mt++)
                #pragma unroll
                for (int nt = 0; nt < 4; nt++)
                    mma_bf16(acc[mt][nt], af[mt], bf[nt]);
        }
        __syncthreads();
    }

    #undef OLOAD
    #undef OSTORE

    const int g = lane >> 2, tg = lane & 3;
    const float gm = gamma[0];
    #pragma unroll
    for (int mt = 0; mt < 4; mt++) {
        int m = m0 + wm * 64 + mt * 16 + g;
        #pragma unroll
        for (int nt = 0; nt < 4; nt++) {
            int n = i0 + wn * 32 + nt * 8 + tg * 2;
            size_t base0 = (size_t)(bb * CC + m) * NP + n;
            size_t base1 = base0 + (size_t)8 * NP;
            const float* r0 = g_out + base0;
            const float* r1 = g_out + base1;
            *(float2*)(dout + base0) =
                make_float2(gm * acc[mt][nt][0] + r0[0], gm * acc[mt][nt][1] + r0[1]);
            *(float2*)(dout + base1) =
                make_float2(gm * acc[mt][nt][2] + r1[0], gm * acc[mt][nt][3] + r1[1]);
        }
    }
}

// ---------------- q and k projections fused (FFMA, small) ----------------
__global__ __launch_bounds__(256) void qk_gemm(const float* __restrict__ wq, const float* __restrict__ bq,
                                               const float* __restrict__ wk, const float* __restrict__ bk) {
    __shared__ float As[8][64];
    __shared__ float Bs[8][128];
    int tid = threadIdx.x, b = blockIdx.z;
    int p0 = blockIdx.x * 128;
    int arow = tid >> 2;
    int acol = (tid & 3) * 2;
    const float* ap = ((arow < 32) ? (wq + arow * CC) : (wk + (arow - 32) * CC)) + acol;
    int brow = tid >> 5, bcol = (tid & 31) * 4;
    const float* bp = g_out + (b * CC + brow) * NP + p0 + bcol;
    int ty = tid >> 4, tx = tid & 15;
    float acc[4][8];
    #pragma unroll
    for (int i = 0; i < 4; i++)
        #pragma unroll
        for (int j = 0; j < 8; j++) acc[i][j] = 0.f;

    for (int it = 0; it < CC / 8; ++it) {
        float2 av = *(const float2*)(ap + it * 8);
        float4 bv = *(const float4*)(bp + (size_t)it * 8 * NP);
        __syncthreads();
        As[acol + 0][arow] = av.x;
        As[acol + 1][arow] = av.y;
        *(float4*)&Bs[brow][bcol] = bv;
        __syncthreads();
        #pragma unroll
        for (int kk = 0; kk < 8; kk++) {
            float a[4], bvv[8];
            float4 t0 = *(const float4*)&As[kk][ty * 4];
            a[0]=t0.x; a[1]=t0.y; a[2]=t0.z; a[3]=t0.w;
            float4 u0 = *(const float4*)&Bs[kk][tx * 8];
            float4 u1 = *(const float4*)&Bs[kk][tx * 8 + 4];
            bvv[0]=u0.x; bvv[1]=u0.y; bvv[2]=u0.z; bvv[3]=u0.w;
            bvv[4]=u1.x; bvv[5]=u1.y; bvv[6]=u1.z; bvv[7]=u1.w;
            #pragma unroll
            for (int i = 0; i < 4; i++)
                #pragma unroll
                for (int j = 0; j < 8; j++)
                    acc[i][j] += a[i] * bvv[j];
        }
    }
    #pragma unroll
    for (int i = 0; i < 4; i++) {
        int row = ty * 4 + i;
        float bias = (row < 32) ? bq[row] : bk[row - 32];
        float* dst = ((row < 32) ? (g_q + (b * C8 + row) * NP)
                                 : (g_k + (b * C8 + row - 32) * NP)) + p0 + tx * 8;
        *(float4*)dst       = make_float4(acc[i][0]+bias, acc[i][1]+bias, acc[i][2]+bias, acc[i][3]+bias);
        *(float4*)(dst + 4) = make_float4(acc[i][4]+bias, acc[i][5]+bias, acc[i][6]+bias, acc[i][7]+bias);
    }
}

// ---------------- row softmax over 4096, bf16 in place (u32-vectorized) ----------------
__global__ __launch_bounds__(256) void softmax_kernel() {
    size_t row = blockIdx.x;
    uint32_t* ptr = (uint32_t*)(g_attnh + row * (size_t)NP);
    int tid = threadIdx.x;
    float vals[16];
    float m = -1e30f;
    #pragma unroll
    for (int s = 0; s < 8; s++) {
        uint32_t u = ptr[tid + s * 256];
        float lo = __bfloat162float(__ushort_as_bfloat16((unsigned short)(u & 0xffff)));
        float hi = __bfloat162float(__ushort_as_bfloat16((unsigned short)(u >> 16)));
        vals[2 * s] = lo; vals[2 * s + 1] = hi;
        m = fmaxf(m, fmaxf(lo, hi));
    }
    #pragma unroll
    for (int o = 16; o; o >>= 1) m = fmaxf(m, __shfl_xor_sync(0xffffffffu, m, o));
    __shared__ float shm[8], shs[8];
    int w = tid >> 5, l = tid & 31;
    if (l == 0) shm[w] = m;
    __syncthreads();
    m = fmaxf(fmaxf(fmaxf(shm[0], shm[1]), fmaxf(shm[2], shm[3])),
              fmaxf(fmaxf(shm[4], shm[5]), fmaxf(shm[6], shm[7])));
    float sum = 0.f;
    #pragma unroll
    for (int s = 0; s < 16; s++) {
        vals[s] = __expf(vals[s] - m);
        sum += vals[s];
    }
    #pragma unroll
    for (int o = 16; o; o >>= 1) sum += __shfl_xor_sync(0xffffffffu, sum, o);
    if (l == 0) shs[w] = sum;
    __syncthreads();
    sum = shs[0] + shs[1] + shs[2] + shs[3] + shs[4] + shs[5] + shs[6] + shs[7];
    float inv = 1.0f / sum;
    #pragma unroll
    for (int s = 0; s < 8; s++)
        ptr[tid + s * 256] = pbf2(vals[2 * s] * inv, vals[2 * s + 1] * inv);
}

// ---------------- launcher: forked-stream capture graph ----------------
extern "C" void kernel_launch(void* const* d_in, const int* in_sizes, int n_in,
                              void* d_out, int out_size) {
    const float* x     = (const float*)d_in[0];
    const float* w1    = (const float*)d_in[1];
    const float* b1    = (const float*)d_in[2];
    const float* w2    = (const float*)d_in[3];
    const float* b2    = (const float*)d_in[4];
    const float* wq    = (const float*)d_in[5];
    const float* bq    = (const float*)d_in[6];
    const float* wk    = (const float*)d_in[7];
    const float* bk    = (const float*)d_in[8];
    const float* wv    = (const float*)d_in[9];
    const float* bv    = (const float*)d_in[10];
    const float* gamma = (const float*)d_in[11];
    float* out = (float*)d_out;

    cudaFuncSetAttribute(tc_gemm<0, KCONV, 0>, cudaFuncAttributeMaxDynamicSharedMemorySize, SMEM_DYN);
    cudaFuncSetAttribute(tc_gemm<0, KCONV, 1>, cudaFuncAttributeMaxDynamicSharedMemorySize, SMEM_DYN);
    cudaFuncSetAttribute(tc_gemm<1, CC, 0>,    cudaFuncAttributeMaxDynamicSharedMemorySize, SMEM_DYN);
    cudaFuncSetAttribute(tc_gemm<2, C8, 0>,    cudaFuncAttributeMaxDynamicSharedMemorySize, SMEM_DYN);
    cudaFuncSetAttribute(o_gemm_bf16,          cudaFuncAttributeMaxDynamicSharedMemorySize, OSMEM);

    // Side stream (created per call, never destroyed: destroying a stream in an
    // active capture invalidates the capture).
    cudaStream_t s1;
    cudaStreamCreateWithFlags(&s1, cudaStreamNonBlocking);
    cudaEvent_t evA, evB, evC, evD;
    cudaEventCreateWithFlags(&evA, cudaEventDisableTiming);
    cudaEventCreateWithFlags(&evB, cudaEventDisableTiming);
    cudaEventCreateWithFlags(&evC, cudaEventDisableTiming);
    cudaEventCreateWithFlags(&evD, cudaEventDisableTiming);

    dim3 g128(NP / 128, CC / 128, BB);   // (32,2,2)

    // fork: wtrans on s1 overlaps pad on main stream
    cudaEventRecord(evA, 0);
    cudaStreamWaitEvent(s1, evA, 0);
    wtrans_kernel<<<dim3(CC, 2), 256, 0, s1>>>(w1, w2);
    pad_kernel<<<BB * CC, 256>>>(x);
    cudaEventRecord(evB, s1);
    cudaStreamWaitEvent(0, evB, 0);

    // conv chain (serial by data dependence)
    tc_gemm<0, KCONV, 0><<<g128, 256, SMEM_DYN>>>(nullptr, b1);
    stats_pad_kernel<<<BB * CC, 256>>>();
    tc_gemm<0, KCONV, 1><<<g128, 256, SMEM_DYN>>>(nullptr, b2);
    stats_norm_kernel<<<BB * CC, 256>>>(x);

    // fork: v-projection (s1) overlaps qk -> energy -> softmax (main)
    cudaEventRecord(evC, 0);
    cudaStreamWaitEvent(s1, evC, 0);
    tc_gemm<1, CC, 0><<<g128, 256, SMEM_DYN, s1>>>(wv, bv);
    qk_gemm<<<dim3(NP / 128, 1, BB), 256>>>(wq, bq, wk, bk);
    tc_gemm<2, C8, 0><<<dim3(NP / 128, NP / 128, BB), 256, SMEM_DYN>>>(nullptr, nullptr);  // energy
    softmax_kernel<<<BB * NP, 256>>>();
    cudaEventRecord(evD, s1);
    cudaStreamWaitEvent(0, evD, 0);

    // join: o-GEMM needs both g_vh (s1) and g_attnh (main)
    o_gemm_bf16<<<g128, 256, OSMEM>>>(gamma, out);
}